// round 11
// baseline (speedup 1.0000x reference)
#include <cuda_runtime.h>
#include <math.h>

// ---------------------------------------------------------------------------
// Problem constants
// ---------------------------------------------------------------------------
#define BB   2
#define SS   2048
#define HH   1024
#define NHH  16
#define HDD  64
#define MM   (BB*SS)      // 4096
#define KK   1024

// Scratch (device globals)
__device__ float g_q[BB*NHH*SS*HDD];
__device__ float g_k[BB*NHH*SS*HDD];
__device__ float g_vt[BB*NHH*HDD*SS];   // V TRANSPOSED: [b,h,d,s]
__device__ float g_attn[BB*NHH*SS*HDD];
__device__ float g_hs[MM*KK];           // tf32-rounded hidden
__device__ float g_wqt[HH*KK];          // weights TRANSPOSED [n][k], tf32-rounded
__device__ float g_wkt[HH*KK];
__device__ float g_wvt[HH*KK];
__device__ float g_wot[HH*KK];
__device__ float g_cost[SS*32];
__device__ float g_sint[SS*32];

// ---------------------------------------------------------------------------
// Helpers (portable sm_80+ only; tcgen05 is rejected by the sm_103 base target)
// ---------------------------------------------------------------------------
__device__ __forceinline__ unsigned f2tf(float x) {
    unsigned u;
    asm("cvt.rna.tf32.f32 %0, %1;" : "=r"(u) : "f"(x));
    return u;
}
__device__ __forceinline__ float f2tf_f(float x) { return __uint_as_float(f2tf(x)); }

__device__ __forceinline__ float ex2(float x) {
    float y;
    asm("ex2.approx.f32 %0, %1;" : "=f"(y) : "f"(x));
    return y;
}

__device__ __forceinline__ void mma_tf32(float& c0, float& c1, float& c2, float& c3,
                                         unsigned a0, unsigned a1, unsigned a2, unsigned a3,
                                         unsigned b0, unsigned b1) {
    asm volatile(
        "mma.sync.aligned.m16n8k8.row.col.f32.tf32.tf32.f32 "
        "{%0,%1,%2,%3}, {%4,%5,%6,%7}, {%8,%9}, {%0,%1,%2,%3};"
        : "+f"(c0), "+f"(c1), "+f"(c2), "+f"(c3)
        : "r"(a0), "r"(a1), "r"(a2), "r"(a3), "r"(b0), "r"(b1));
}

__device__ __forceinline__ unsigned smem_u32(const void* p) {
    unsigned a;
    asm("{ .reg .u64 t; cvta.to.shared.u64 t, %1; cvt.u32.u64 %0, t; }"
        : "=r"(a) : "l"(p));
    return a;
}
__device__ __forceinline__ void cp16(unsigned s, const void* g) {
    asm volatile("cp.async.cg.shared.global [%0], [%1], 16;" :: "r"(s), "l"(g));
}
#define CP_COMMIT() asm volatile("cp.async.commit_group;" ::: "memory")
#define CP_WAIT0()  asm volatile("cp.async.wait_group 0;" ::: "memory")

// ---------------------------------------------------------------------------
// Prep: round hidden to tf32 + RoPE table (merged, one launch)
// ---------------------------------------------------------------------------
__device__ __forceinline__ float4 round4(float4 v) {
    return make_float4(f2tf_f(v.x), f2tf_f(v.y), f2tf_f(v.z), f2tf_f(v.w));
}
__global__ void prep_kernel(const float* __restrict__ hs) {
    int i = blockIdx.x * blockDim.x + threadIdx.x;   // 0 .. 1048575
    ((float4*)g_hs)[i] = round4(((const float4*)hs)[i]);
    if (i < SS * 32) {
        int s = i >> 5, j = i & 31;
        float inv = expf(-((float)(2 * j) / 64.0f) * 9.210340371976184f);
        float ang = (float)s * inv;
        float c, sn;
        sincosf(ang, &sn, &c);
        g_cost[i] = c;
        g_sint[i] = sn;
    }
}

// ---------------------------------------------------------------------------
// Transpose + tf32-round the 4 weight matrices: [k][n] -> [n][k]
// ---------------------------------------------------------------------------
__global__ void pre_round_w(const float* __restrict__ wq, const float* __restrict__ wk,
                            const float* __restrict__ wv, const float* __restrict__ wo) {
    __shared__ float t[32][33];
    const int z = blockIdx.z;
    const float* src = (z == 0) ? wq : (z == 1) ? wk : (z == 2) ? wv : wo;
    float* dst = (z == 0) ? g_wqt : (z == 1) ? g_wkt : (z == 2) ? g_wvt : g_wot;
    const int k0 = blockIdx.x * 32, n0 = blockIdx.y * 32;
    #pragma unroll
    for (int i = 0; i < 4; i++) {
        int ky = threadIdx.y + i * 8;
        t[ky][threadIdx.x] = f2tf_f(src[(size_t)(k0 + ky) * HH + n0 + threadIdx.x]);
    }
    __syncthreads();
    #pragma unroll
    for (int i = 0; i < 4; i++) {
        int ny = threadIdx.y + i * 8;
        dst[(size_t)(n0 + ny) * KK + k0 + threadIdx.x] = t[threadIdx.x][ny];
    }
}

// ---------------------------------------------------------------------------
// tf32 mma.sync GEMM v2: 128x64 CTA tile, k-chunk 64, 16 chunks (HALF the
// wait/barrier events of v1), 128 threads, 4 warps x (64x32) tiles,
// 2-stage cp.async, smem 110.6KB -> 2 CTAs/SM.
// Both operands k-contiguous (B = transposed weights) -> all LDS.64.
// ---------------------------------------------------------------------------
#define GST 72
#define ASTAGE (128*GST)                 // 9216 floats
#define BSTAGE (64*GST)                  // 4608 floats
#define STAGE_FLOATS (ASTAGE + BSTAGE)   // 13824
#define GEMM_SMEM (2 * STAGE_FLOATS * 4) // 110592 B
#define CST 68

__device__ __forceinline__ void gemm_chunk_v2(const float* __restrict__ As,
                                              const float* __restrict__ Bs,
                                              float acc[4][4][4],
                                              int wm, int wn, int g, int j) {
    #pragma unroll
    for (int kk2 = 0; kk2 < 8; kk2++) {
        unsigned a[4][4], bf[4][2];
        #pragma unroll
        for (int mt = 0; mt < 4; mt++) {
            int rb = (wm * 64 + mt * 16 + g) * GST + kk2 * 8 + 2 * j;
            float2 lo = *(const float2*)&As[rb];
            float2 hi = *(const float2*)&As[rb + 8 * GST];
            a[mt][0] = __float_as_uint(lo.x);
            a[mt][2] = __float_as_uint(lo.y);
            a[mt][1] = __float_as_uint(hi.x);
            a[mt][3] = __float_as_uint(hi.y);
        }
        #pragma unroll
        for (int nt = 0; nt < 4; nt++) {
            int cb = (wn * 32 + nt * 8 + g) * GST + kk2 * 8 + 2 * j;
            float2 bv = *(const float2*)&Bs[cb];
            bf[nt][0] = __float_as_uint(bv.x);
            bf[nt][1] = __float_as_uint(bv.y);
        }
        #pragma unroll
        for (int mt = 0; mt < 4; mt++)
            #pragma unroll
            for (int nt = 0; nt < 4; nt++)
                mma_tf32(acc[mt][nt][0], acc[mt][nt][1], acc[mt][nt][2], acc[mt][nt][3],
                         a[mt][0], a[mt][1], a[mt][2], a[mt][3],
                         bf[nt][0], bf[nt][1]);
    }
}

// which: 0=q(rope) 1=k(rope) 2=v(transposed output). n-tile = one head.
__global__ __launch_bounds__(128) void qkv_mma(
    const float* __restrict__ bq, const float* __restrict__ bk, const float* __restrict__ bv)
{
    extern __shared__ float sm[];
    const int which = blockIdx.z;
    const float* WT   = (which == 0) ? g_wqt : (which == 1) ? g_wkt : g_wvt;
    const float* bias = (which == 0) ? bq    : (which == 1) ? bk    : bv;

    const int head = blockIdx.x;                 // 16 heads = n-tiles of 64
    const int n0 = head * 64, m0 = blockIdx.y * 128;
    const int tid = threadIdx.x, wid = tid >> 5, lane = tid & 31;
    const int g = lane >> 2, j = lane & 3;
    const int wm = wid & 1, wn = wid >> 1;
    const unsigned sb = smem_u32(sm);

    auto stage = [&](int c) {
        const int k0 = c * 64;
        const unsigned bufb = sb + ((c & 1) * STAGE_FLOATS) * 4;
        #pragma unroll
        for (int i = 0; i < 16; i++) {
            int idx = tid + i * 128, r = idx >> 4, c4 = idx & 15;
            cp16(bufb + (r * GST + c4 * 4) * 4, &g_hs[(size_t)(m0 + r) * KK + k0 + c4 * 4]);
        }
        #pragma unroll
        for (int i = 0; i < 8; i++) {
            int idx = tid + i * 128, r = idx >> 4, c4 = idx & 15;
            cp16(bufb + (ASTAGE + r * GST + c4 * 4) * 4,
                 &WT[(size_t)(n0 + r) * KK + k0 + c4 * 4]);
        }
        CP_COMMIT();
    };

    float acc[4][4][4] = {};
    stage(0);
    for (int c = 0; c < 16; c++) {
        CP_WAIT0();
        __syncthreads();
        if (c < 15) stage(c + 1);
        const float* As = sm + (c & 1) * STAGE_FLOATS;
        gemm_chunk_v2(As, As + ASTAGE, acc, wm, wn, g, j);
    }
    __syncthreads();

    float* Cs = sm;
    #pragma unroll
    for (int mt = 0; mt < 4; mt++)
        #pragma unroll
        for (int nt = 0; nt < 4; nt++) {
            int r = wm * 64 + mt * 16 + g, cc = wn * 32 + nt * 8 + 2 * j;
            *(float2*)&Cs[r * CST + cc]       = make_float2(acc[mt][nt][0], acc[mt][nt][1]);
            *(float2*)&Cs[(r + 8) * CST + cc] = make_float2(acc[mt][nt][2], acc[mt][nt][3]);
        }
    __syncthreads();

    if (which != 2) {
        float* out = (which == 0) ? g_q : g_k;
        #pragma unroll 4
        for (int it = 0; it < 32; it++) {
            int p = it * 128 + tid;          // 128 rows x 32 pairs
            int r = p >> 5, jj = p & 31;
            int m = m0 + r, bb = m >> 11, s = m & 2047;
            float x1 = Cs[r * CST + jj]      + bias[head * 64 + jj];
            float x2 = Cs[r * CST + jj + 32] + bias[head * 64 + jj + 32];
            float cs = g_cost[s * 32 + jj], sn = g_sint[s * 32 + jj];
            float* op = out + ((size_t)(bb * NHH + head) * SS + s) * HDD;
            op[jj]      = f2tf_f(x1 * cs - x2 * sn);
            op[jj + 32] = f2tf_f(x1 * sn + x2 * cs);
        }
    } else {
        // V: write TRANSPOSED [b,h,d,s]; consecutive tid -> consecutive s
        #pragma unroll 4
        for (int it = 0; it < 64; it++) {
            int p = it * 128 + tid;          // 64 cols x 128 rows
            int r = p & 127, d = p >> 7;
            int m = m0 + r, bb = m >> 11, s = m & 2047;
            g_vt[((size_t)(bb * NHH + head) * HDD + d) * SS + s] =
                f2tf_f(Cs[r * CST + d] + bias[head * 64 + d]);
        }
    }
}

__global__ __launch_bounds__(128) void proj_mma(
    const float* __restrict__ bo, float* __restrict__ outp)
{
    extern __shared__ float sm[];
    const int n0 = blockIdx.x * 64, m0 = blockIdx.y * 128;
    const int tid = threadIdx.x, wid = tid >> 5, lane = tid & 31;
    const int g = lane >> 2, j = lane & 3;
    const int wm = wid & 1, wn = wid >> 1;
    const unsigned sb = smem_u32(sm);

    auto stage = [&](int c) {
        // k-chunk 64 == one head: A rows come from g_attn head c
        const unsigned bufb = sb + ((c & 1) * STAGE_FLOATS) * 4;
        #pragma unroll
        for (int i = 0; i < 16; i++) {
            int idx = tid + i * 128, r = idx >> 4, c4 = idx & 15;
            int m = m0 + r, bb = m >> 11, s = m & 2047;
            cp16(bufb + (r * GST + c4 * 4) * 4,
                 &g_attn[((size_t)(bb * NHH + c) * SS + s) * HDD + c4 * 4]);
        }
        #pragma unroll
        for (int i = 0; i < 8; i++) {
            int idx = tid + i * 128, r = idx >> 4, c4 = idx & 15;
            cp16(bufb + (ASTAGE + r * GST + c4 * 4) * 4,
                 &g_wot[(size_t)(n0 + r) * KK + c * 64 + c4 * 4]);
        }
        CP_COMMIT();
    };

    float acc[4][4][4] = {};
    stage(0);
    for (int c = 0; c < 16; c++) {
        CP_WAIT0();
        __syncthreads();
        if (c < 15) stage(c + 1);
        const float* As = sm + (c & 1) * STAGE_FLOATS;
        gemm_chunk_v2(As, As + ASTAGE, acc, wm, wn, g, j);
    }
    __syncthreads();

    float* Cs = sm;
    #pragma unroll
    for (int mt = 0; mt < 4; mt++)
        #pragma unroll
        for (int nt = 0; nt < 4; nt++) {
            int r = wm * 64 + mt * 16 + g, cc = wn * 32 + nt * 8 + 2 * j;
            *(float2*)&Cs[r * CST + cc]       = make_float2(acc[mt][nt][0], acc[mt][nt][1]);
            *(float2*)&Cs[(r + 8) * CST + cc] = make_float2(acc[mt][nt][2], acc[mt][nt][3]);
        }
    __syncthreads();

    #pragma unroll 4
    for (int i = 0; i < 16; i++) {
        int idx = tid + i * 128;             // 128 rows x 16 float4
        int r = idx >> 4, c4 = idx & 15;
        float4 v = *(float4*)&Cs[r * CST + c4 * 4];
        float4 bv = *(const float4*)&bo[n0 + c4 * 4];
        v.x += bv.x; v.y += bv.y; v.z += bv.z; v.w += bv.w;
        *(float4*)&outp[(size_t)(m0 + r) * HH + n0 + c4 * 4] = v;
    }
}

// ---------------------------------------------------------------------------
// Flash attention (unchanged from R8): 128-row CTA tile, 4 warps x 32 rows,
// no-max softmax, V transposed [d][s] LDS.64 B-frags, 2 CTAs/SM.
// ---------------------------------------------------------------------------
#define QST 72
#define VST 72
#define ATTN_SMEM ((128*QST + 2*64*QST + 2*64*VST) * 4)   // 110592 B

__global__ __launch_bounds__(128, 2) void attn_kernel()
{
    extern __shared__ float sm[];
    float* Qs = sm;
    float* Ks = Qs + 128 * QST;
    float* Vs = Ks + 2 * 64 * QST;

    const int qt = gridDim.x - 1 - blockIdx.x;
    const int head = blockIdx.y, b = blockIdx.z;
    const int tid = threadIdx.x, wid = tid >> 5, lane = tid & 31;
    const int g = lane >> 2, j = lane & 3;
    const int r0 = wid * 32;
    const size_t base  = (size_t)(b * NHH + head) * SS * HDD;
    const size_t basev = (size_t)(b * NHH + head) * HDD * SS;
    const int q0 = qt * 128;
    const int rA = q0 + r0 + g, rB = rA + 8, rC = rA + 16, rD = rA + 24;

    const unsigned ks_base = smem_u32(Ks), vs_base = smem_u32(Vs);
    const float QSCALE = 0.125f * 1.4426950408889634f;

    #pragma unroll
    for (int i = 0; i < 16; i++) {
        int idx = tid + i * 128;
        int r = idx >> 4, c4 = idx & 15;
        float4 v = *(const float4*)&g_q[base + (size_t)(q0 + r) * HDD + c4 * 4];
        *(float4*)&Qs[r * QST + c4 * 4] =
            make_float4(v.x * QSCALE, v.y * QSCALE, v.z * QSCALE, v.w * QSCALE);
    }

    #pragma unroll
    for (int i = 0; i < 8; i++) {
        int idx = tid + i * 128;
        int r = idx >> 4, c4 = idx & 15;
        cp16(ks_base + (r * QST + c4 * 4) * 4, &g_k[base + (size_t)r * HDD + c4 * 4]);
        cp16(vs_base + (r * VST + c4 * 4) * 4, &g_vt[basev + (size_t)r * SS + c4 * 4]);
    }
    CP_COMMIT();

    const int ntiles = 2 * qt + 2;
    float oa0[8] = {}, oa1[8] = {}, oa2[8] = {}, oa3[8] = {};
    float ob0[8] = {}, ob1[8] = {}, ob2[8] = {}, ob3[8] = {};
    float lA = 0.0f, lB = 0.0f, lC = 0.0f, lD = 0.0f;

    for (int kt = 0; kt < ntiles; kt++) {
        const int bf = kt & 1;
        CP_WAIT0();
        __syncthreads();

        if (kt + 1 < ntiles) {
            const int nb = bf ^ 1, k0n = (kt + 1) * 64;
            #pragma unroll
            for (int i = 0; i < 8; i++) {
                int idx = tid + i * 128;
                int r = idx >> 4, c4 = idx & 15;
                cp16(ks_base + (nb * 64 * QST + r * QST + c4 * 4) * 4,
                     &g_k[base + (size_t)(k0n + r) * HDD + c4 * 4]);
                cp16(vs_base + (nb * 64 * VST + r * VST + c4 * 4) * 4,
                     &g_vt[basev + (size_t)r * SS + k0n + c4 * 4]);
            }
            CP_COMMIT();
        }
        const int k0 = kt * 64;
        if (k0 > q0 + r0 + 31) continue;

        const float* Kb = Ks + bf * 64 * QST;
        const float* Vb = Vs + bf * 64 * VST;

        float sa0[8] = {}, sa1[8] = {}, sa2[8] = {}, sa3[8] = {};
        float sb0[8] = {}, sb1[8] = {}, sb2[8] = {}, sb3[8] = {};
        #pragma unroll
        for (int kk = 0; kk < 8; kk++) {
            float2 qa = *(const float2*)&Qs[(r0 + g)      * QST + kk * 8 + 2 * j];
            float2 qb = *(const float2*)&Qs[(r0 + g + 8)  * QST + kk * 8 + 2 * j];
            float2 qc = *(const float2*)&Qs[(r0 + g + 16) * QST + kk * 8 + 2 * j];
            float2 qd = *(const float2*)&Qs[(r0 + g + 24) * QST + kk * 8 + 2 * j];
            unsigned a0 = __float_as_uint(qa.x), a2 = __float_as_uint(qa.y);
            unsigned a1 = __float_as_uint(qb.x), a3 = __float_as_uint(qb.y);
            unsigned c0 = __float_as_uint(qc.x), c2 = __float_as_uint(qc.y);
            unsigned c1 = __float_as_uint(qd.x), c3 = __float_as_uint(qd.y);
            #pragma unroll
            for (int nt = 0; nt < 8; nt++) {
                float2 kv = *(const float2*)&Kb[(nt * 8 + g) * QST + kk * 8 + 2 * j];
                unsigned b0 = __float_as_uint(kv.x), b1 = __float_as_uint(kv.y);
                mma_tf32(sa0[nt], sa1[nt], sa2[nt], sa3[nt], a0, a1, a2, a3, b0, b1);
                mma_tf32(sb0[nt], sb1[nt], sb2[nt], sb3[nt], c0, c1, c2, c3, b0, b1);
            }
        }

        const bool dmA = (k0 + 63) > (q0 + r0);
        const bool dmB = (k0 + 63) > (q0 + r0 + 16);
        #pragma unroll
        for (int nt = 0; nt < 8; nt++) {
            int col = k0 + nt * 8 + 2 * j;
            if (dmA) {
                if (col     > rA) sa0[nt] = -1.0e30f;
                if (col + 1 > rA) sa1[nt] = -1.0e30f;
                if (col     > rB) sa2[nt] = -1.0e30f;
                if (col + 1 > rB) sa3[nt] = -1.0e30f;
            }
            if (dmB) {
                if (col     > rC) sb0[nt] = -1.0e30f;
                if (col + 1 > rC) sb1[nt] = -1.0e30f;
                if (col     > rD) sb2[nt] = -1.0e30f;
                if (col + 1 > rD) sb3[nt] = -1.0e30f;
            }
            float p0 = ex2(sa0[nt]), p1 = ex2(sa1[nt]);
            float p2 = ex2(sa2[nt]), p3 = ex2(sa3[nt]);
            float p4 = ex2(sb0[nt]), p5 = ex2(sb1[nt]);
            float p6 = ex2(sb2[nt]), p7 = ex2(sb3[nt]);
            lA += p0 + p1; lB += p2 + p3; lC += p4 + p5; lD += p6 + p7;
            sa0[nt] = f2tf_f(p0); sa1[nt] = f2tf_f(p1);
            sa2[nt] = f2tf_f(p2); sa3[nt] = f2tf_f(p3);
            sb0[nt] = f2tf_f(p4); sb1[nt] = f2tf_f(p5);
            sb2[nt] = f2tf_f(p6); sb3[nt] = f2tf_f(p7);
        }

        #pragma unroll
        for (int kk = 0; kk < 8; kk++) {
            unsigned a0 = __float_as_uint(sa0[kk]);
            unsigned a1 = __float_as_uint(sa2[kk]);
            unsigned a2 = __float_as_uint(sa1[kk]);
            unsigned a3 = __float_as_uint(sa3[kk]);
            unsigned c0 = __float_as_uint(sb0[kk]);
            unsigned c1 = __float_as_uint(sb2[kk]);
            unsigned c2 = __float_as_uint(sb1[kk]);
            unsigned c3 = __float_as_uint(sb3[kk]);
            #pragma unroll
            for (int nt = 0; nt < 8; nt++) {
                float2 vv = *(const float2*)&Vb[(nt * 8 + g) * VST + kk * 8 + 2 * j];
                unsigned b0 = __float_as_uint(vv.x), b1 = __float_as_uint(vv.y);
                mma_tf32(oa0[nt], oa1[nt], oa2[nt], oa3[nt], a0, a1, a2, a3, b0, b1);
                mma_tf32(ob0[nt], ob1[nt], ob2[nt], ob3[nt], c0, c1, c2, c3, b0, b1);
            }
        }
    }

    lA += __shfl_xor_sync(0xffffffffu, lA, 1);
    lA += __shfl_xor_sync(0xffffffffu, lA, 2);
    lB += __shfl_xor_sync(0xffffffffu, lB, 1);
    lB += __shfl_xor_sync(0xffffffffu, lB, 2);
    lC += __shfl_xor_sync(0xffffffffu, lC, 1);
    lC += __shfl_xor_sync(0xffffffffu, lC, 2);
    lD += __shfl_xor_sync(0xffffffffu, lD, 1);
    lD += __shfl_xor_sync(0xffffffffu, lD, 2);

    {
        float liA = 1.0f / lA, liB = 1.0f / lB, liC = 1.0f / lC, liD = 1.0f / lD;
        #pragma unroll
        for (int nt = 0; nt < 8; nt++) {
            int col = nt * 8 + 2 * j;
            *(float2*)&g_attn[base + (size_t)rA * HDD + col] =
                make_float2(f2tf_f(oa0[nt] * liA), f2tf_f(oa1[nt] * liA));
            *(float2*)&g_attn[base + (size_t)rB * HDD + col] =
                make_float2(f2tf_f(oa2[nt] * liB), f2tf_f(oa3[nt] * liB));
            *(float2*)&g_attn[base + (size_t)rC * HDD + col] =
                make_float2(f2tf_f(ob0[nt] * liC), f2tf_f(ob1[nt] * liC));
            *(float2*)&g_attn[base + (size_t)rD * HDD + col] =
                make_float2(f2tf_f(ob2[nt] * liD), f2tf_f(ob3[nt] * liD));
        }
    }
}

// ---------------------------------------------------------------------------
extern "C" void kernel_launch(void* const* d_in, const int* in_sizes, int n_in,
                              void* d_out, int out_size)
{
    const float* hs = (const float*)d_in[0];
    // d_in[1] = attention_mask (fixed causal) -- handled analytically
    const float* wq = (const float*)d_in[2];
    const float* bq = (const float*)d_in[3];
    const float* wk = (const float*)d_in[4];
    const float* bk = (const float*)d_in[5];
    const float* wv = (const float*)d_in[6];
    const float* bv = (const float*)d_in[7];
    const float* wo = (const float*)d_in[8];
    const float* bo = (const float*)d_in[9];
    float* out = (float*)d_out;

    prep_kernel<<<(MM * KK / 4) / 256, 256>>>(hs);
    pre_round_w<<<dim3(KK / 32, HH / 32, 4), dim3(32, 8)>>>(wq, wk, wv, wo);

    cudaFuncSetAttribute(qkv_mma,  cudaFuncAttributeMaxDynamicSharedMemorySize, GEMM_SMEM);
    cudaFuncSetAttribute(proj_mma, cudaFuncAttributeMaxDynamicSharedMemorySize, GEMM_SMEM);
    cudaFuncSetAttribute(attn_kernel, cudaFuncAttributeMaxDynamicSharedMemorySize, ATTN_SMEM);

    qkv_mma<<<dim3(NHH, 32, 3), 128, GEMM_SMEM>>>(bq, bk, bv);
    attn_kernel<<<dim3(SS / 128, NHH, BB), 128, ATTN_SMEM>>>();
    proj_mma<<<dim3(NHH, 32), 128, GEMM_SMEM>>>(bo, out);
}

// round 13
// speedup vs baseline: 1.5201x; 1.5201x over previous
#include <cuda_runtime.h>
#include <cuda_fp16.h>
#include <math.h>

// ---------------------------------------------------------------------------
// Problem constants
// ---------------------------------------------------------------------------
#define BB   2
#define SS   2048
#define HH   1024
#define NHH  16
#define HDD  64
#define MM   (BB*SS)      // 4096
#define KK   1024

// k-permutation within each 16-group: thread j's m16n8k16 fragment halves
// {2j,2j+1,2j+8,2j+9} become contiguous -> single LDS.64 per fragment.
#define KPOS(k) ((((k)&6)<<1) + ((((k)>>3)&1)<<1) + ((k)&1))

// Scratch (device globals) — fp16, k-permuted where contracted
__device__ __half g_q[BB*NHH*SS*HDD];     // [b,h,s,d] d-permuted, pre-scaled
__device__ __half g_k[BB*NHH*SS*HDD];     // [b,h,s,d] d-permuted
__device__ __half g_vt[BB*NHH*HDD*SS];    // [b,h,d,s] s-permuted
__device__ __half g_attn[BB*NHH*SS*HDD];  // [b,h,s,d] d-permuted
__device__ __half g_hs[MM*KK];            // [m][k]    k-permuted
__device__ __half g_wqt[HH*KK];           // [n][k]    k-permuted
__device__ __half g_wkt[HH*KK];
__device__ __half g_wvt[HH*KK];
__device__ __half g_wot[HH*KK];
__device__ float  g_cost[SS*32];
__device__ float  g_sint[SS*32];

// ---------------------------------------------------------------------------
// Helpers
// ---------------------------------------------------------------------------
__device__ __forceinline__ float ex2(float x) {
    float y;
    asm("ex2.approx.f32 %0, %1;" : "=f"(y) : "f"(x));
    return y;
}
__device__ __forceinline__ unsigned pack_h2(float lo, float hi) {
    unsigned r;
    asm("cvt.rn.f16x2.f32 %0, %1, %2;" : "=r"(r) : "f"(hi), "f"(lo));
    return r;
}
__device__ __forceinline__ void mma_f16(float& c0, float& c1, float& c2, float& c3,
                                        unsigned a0, unsigned a1, unsigned a2, unsigned a3,
                                        unsigned b0, unsigned b1) {
    asm volatile(
        "mma.sync.aligned.m16n8k16.row.col.f32.f16.f16.f32 "
        "{%0,%1,%2,%3}, {%4,%5,%6,%7}, {%8,%9}, {%0,%1,%2,%3};"
        : "+f"(c0), "+f"(c1), "+f"(c2), "+f"(c3)
        : "r"(a0), "r"(a1), "r"(a2), "r"(a3), "r"(b0), "r"(b1));
}
__device__ __forceinline__ unsigned smem_u32(const void* p) {
    unsigned a;
    asm("{ .reg .u64 t; cvta.to.shared.u64 t, %1; cvt.u32.u64 %0, t; }"
        : "=r"(a) : "l"(p));
    return a;
}
__device__ __forceinline__ void cp16(unsigned s, const void* g) {
    asm volatile("cp.async.cg.shared.global [%0], [%1], 16;" :: "r"(s), "l"(g));
}
#define CP_COMMIT() asm volatile("cp.async.commit_group;" ::: "memory")
#define CP_WAIT0()  asm volatile("cp.async.wait_group 0;" ::: "memory")

// ---------------------------------------------------------------------------
// Prep: hidden fp32 -> fp16 k-permuted; RoPE table
// one thread per 16-k group (262144 threads)
// ---------------------------------------------------------------------------
__global__ void prep_kernel(const float* __restrict__ hs) {
    int i = blockIdx.x * blockDim.x + threadIdx.x;   // 0..262143
    const float4* src = (const float4*)(hs + (size_t)i * 16);
    float4 v0 = src[0], v1 = src[1], v2 = src[2], v3 = src[3];
    // logical halves: v0=k0..3, v1=k4..7, v2=k8..11, v3=k12..15
    uint4 o0, o1;
    o0.x = pack_h2(v0.x, v0.y);   // pos 0,1   = k0,1
    o0.y = pack_h2(v2.x, v2.y);   // pos 2,3   = k8,9
    o0.z = pack_h2(v0.z, v0.w);   // pos 4,5   = k2,3
    o0.w = pack_h2(v2.z, v2.w);   // pos 6,7   = k10,11
    o1.x = pack_h2(v1.x, v1.y);   // pos 8,9   = k4,5
    o1.y = pack_h2(v3.x, v3.y);   // pos 10,11 = k12,13
    o1.z = pack_h2(v1.z, v1.w);   // pos 12,13 = k6,7
    o1.w = pack_h2(v3.z, v3.w);   // pos 14,15 = k14,15
    uint4* dst = (uint4*)(g_hs + (size_t)i * 16);
    dst[0] = o0; dst[1] = o1;

    if (i < SS * 32) {
        int s = i >> 5, j = i & 31;
        float inv = expf(-((float)(2 * j) / 64.0f) * 9.210340371976184f);
        float ang = (float)s * inv;
        float c, sn;
        sincosf(ang, &sn, &c);
        g_cost[i] = c;
        g_sint[i] = sn;
    }
}

// ---------------------------------------------------------------------------
// Transpose + fp16 + k-permute the 4 weight matrices: [k][n] -> [n][k]
// ---------------------------------------------------------------------------
__global__ void pre_round_w(const float* __restrict__ wq, const float* __restrict__ wk,
                            const float* __restrict__ wv, const float* __restrict__ wo) {
    __shared__ float t[32][33];
    const int z = blockIdx.z;
    const float* src = (z == 0) ? wq : (z == 1) ? wk : (z == 2) ? wv : wo;
    __half* dst = (z == 0) ? g_wqt : (z == 1) ? g_wkt : (z == 2) ? g_wvt : g_wot;
    const int k0 = blockIdx.x * 32, n0 = blockIdx.y * 32;
    #pragma unroll
    for (int i = 0; i < 4; i++) {
        int ky = threadIdx.y + i * 8;
        t[ky][threadIdx.x] = src[(size_t)(k0 + ky) * HH + n0 + threadIdx.x];
    }
    __syncthreads();
    int kx = threadIdx.x;
    int kp = k0 + (kx & ~15) + KPOS(kx & 15);
    #pragma unroll
    for (int i = 0; i < 4; i++) {
        int ny = threadIdx.y + i * 8;
        dst[(size_t)(n0 + ny) * KK + kp] = __float2half_rn(t[kx][ny]);
    }
}

// ---------------------------------------------------------------------------
// fp16 mma GEMM: 128x64 CTA tile, k-chunk 64, 16 chunks, 128 threads,
// 4 warps x (64x32), 2-stage cp.async. Row stride 88 halves (176B) —
// conflict-free LDS.64 fragments. smem 67.6KB.
// ---------------------------------------------------------------------------
#define RSTB 176                          // row stride bytes (88 halves)
#define ASTAGE_B (128*RSTB)               // 22528
#define BSTAGE_B (64*RSTB)                // 11264
#define STAGE_B  (ASTAGE_B + BSTAGE_B)    // 33792
#define GEMM_SMEM (2 * STAGE_B)           // 67584
#define CST 68

__device__ __forceinline__ void gemm_chunk_f16(const char* As, const char* Bs,
                                               float acc[4][4][4],
                                               int wm, int wn, int g, int j) {
    #pragma unroll
    for (int kg = 0; kg < 4; kg++) {
        const int kb = (kg * 16 + 4 * j) * 2;
        uint2 a[4][2], bv[4];
        #pragma unroll
        for (int mt = 0; mt < 4; mt++) {
            int r = wm * 64 + mt * 16 + g;
            a[mt][0] = *(const uint2*)(As + r * RSTB + kb);
            a[mt][1] = *(const uint2*)(As + (r + 8) * RSTB + kb);
        }
        #pragma unroll
        for (int nt = 0; nt < 4; nt++) {
            int rr = wn * 32 + nt * 8 + g;
            bv[nt] = *(const uint2*)(Bs + rr * RSTB + kb);
        }
        #pragma unroll
        for (int mt = 0; mt < 4; mt++)
            #pragma unroll
            for (int nt = 0; nt < 4; nt++)
                mma_f16(acc[mt][nt][0], acc[mt][nt][1], acc[mt][nt][2], acc[mt][nt][3],
                        a[mt][0].x, a[mt][1].x, a[mt][0].y, a[mt][1].y,
                        bv[nt].x, bv[nt].y);
    }
}

// which: 0=q(rope,scaled) 1=k(rope) 2=v(transposed). n-tile = one head.
__global__ __launch_bounds__(128) void qkv_mma(
    const float* __restrict__ bq, const float* __restrict__ bk, const float* __restrict__ bv)
{
    extern __shared__ char smc[];
    const int which = blockIdx.z;
    const __half* WT  = (which == 0) ? g_wqt : (which == 1) ? g_wkt : g_wvt;
    const float* bias = (which == 0) ? bq    : (which == 1) ? bk    : bv;

    const int head = blockIdx.x;
    const int n0 = head * 64, m0 = blockIdx.y * 128;
    const int tid = threadIdx.x, wid = tid >> 5, lane = tid & 31;
    const int g = lane >> 2, j = lane & 3;
    const int wm = wid & 1, wn = wid >> 1;
    const unsigned sb = smem_u32(smc);

    auto stage = [&](int c) {
        const int k0 = c * 64;
        const unsigned bufb = sb + (c & 1) * STAGE_B;
        #pragma unroll
        for (int i = 0; i < 8; i++) {
            int idx = tid + i * 128, r = idx >> 3, c8 = idx & 7;
            cp16(bufb + r * RSTB + c8 * 16, &g_hs[(size_t)(m0 + r) * KK + k0 + c8 * 8]);
        }
        #pragma unroll
        for (int i = 0; i < 4; i++) {
            int idx = tid + i * 128, r = idx >> 3, c8 = idx & 7;
            cp16(bufb + ASTAGE_B + r * RSTB + c8 * 16,
                 &WT[(size_t)(n0 + r) * KK + k0 + c8 * 8]);
        }
        CP_COMMIT();
    };

    float acc[4][4][4] = {};
    stage(0);
    for (int c = 0; c < 16; c++) {
        CP_WAIT0();
        __syncthreads();
        if (c < 15) stage(c + 1);
        const char* As = smc + (c & 1) * STAGE_B;
        gemm_chunk_f16(As, As + ASTAGE_B, acc, wm, wn, g, j);
    }
    __syncthreads();

    float* Cs = (float*)smc;
    #pragma unroll
    for (int mt = 0; mt < 4; mt++)
        #pragma unroll
        for (int nt = 0; nt < 4; nt++) {
            int r = wm * 64 + mt * 16 + g, cc = wn * 32 + nt * 8 + 2 * j;
            *(float2*)&Cs[r * CST + cc]       = make_float2(acc[mt][nt][0], acc[mt][nt][1]);
            *(float2*)&Cs[(r + 8) * CST + cc] = make_float2(acc[mt][nt][2], acc[mt][nt][3]);
        }
    __syncthreads();

    const float QSCALE = 0.125f * 1.4426950408889634f;
    if (which != 2) {
        __half* out = (which == 0) ? g_q : g_k;
        const float scale = (which == 0) ? QSCALE : 1.0f;
        #pragma unroll 4
        for (int it = 0; it < 32; it++) {
            int p = it * 128 + tid;          // 128 rows x 32 pairs
            int r = p >> 5, jj = p & 31;
            int m = m0 + r, bb = m >> 11, s = m & 2047;
            float x1 = Cs[r * CST + jj]      + bias[head * 64 + jj];
            float x2 = Cs[r * CST + jj + 32] + bias[head * 64 + jj + 32];
            float cs = g_cost[s * 32 + jj], sn = g_sint[s * 32 + jj];
            __half* op = out + ((size_t)(bb * NHH + head) * SS + s) * HDD;
            int d1 = jj, d2 = jj + 32;
            op[(d1 & ~15) + KPOS(d1 & 15)] = __float2half_rn((x1 * cs - x2 * sn) * scale);
            op[(d2 & ~15) + KPOS(d2 & 15)] = __float2half_rn((x1 * sn + x2 * cs) * scale);
        }
    } else {
        #pragma unroll 4
        for (int it = 0; it < 64; it++) {
            int p = it * 128 + tid;          // 64 d-cols x 128 rows
            int r = p & 127, d = p >> 7;
            int m = m0 + r, bb = m >> 11, s = m & 2047;
            int spos = (s & ~15) + KPOS(s & 15);
            g_vt[((size_t)(bb * NHH + head) * HDD + d) * SS + spos] =
                __float2half_rn(Cs[r * CST + d] + bias[head * 64 + d]);
        }
    }
}

__global__ __launch_bounds__(128) void proj_mma(
    const float* __restrict__ bo, float* __restrict__ outp)
{
    extern __shared__ char smc[];
    const int n0 = blockIdx.x * 64, m0 = blockIdx.y * 128;
    const int tid = threadIdx.x, wid = tid >> 5, lane = tid & 31;
    const int g = lane >> 2, j = lane & 3;
    const int wm = wid & 1, wn = wid >> 1;
    const unsigned sb = smem_u32(smc);

    auto stage = [&](int c) {
        const unsigned bufb = sb + (c & 1) * STAGE_B;
        #pragma unroll
        for (int i = 0; i < 8; i++) {
            int idx = tid + i * 128, r = idx >> 3, c8 = idx & 7;
            int m = m0 + r, bb = m >> 11, s = m & 2047;
            cp16(bufb + r * RSTB + c8 * 16,
                 &g_attn[((size_t)(bb * NHH + c) * SS + s) * HDD + c8 * 8]);
        }
        #pragma unroll
        for (int i = 0; i < 4; i++) {
            int idx = tid + i * 128, r = idx >> 3, c8 = idx & 7;
            cp16(bufb + ASTAGE_B + r * RSTB + c8 * 16,
                 &g_wot[(size_t)(n0 + r) * KK + c * 64 + c8 * 8]);
        }
        CP_COMMIT();
    };

    float acc[4][4][4] = {};
    stage(0);
    for (int c = 0; c < 16; c++) {
        CP_WAIT0();
        __syncthreads();
        if (c < 15) stage(c + 1);
        const char* As = smc + (c & 1) * STAGE_B;
        gemm_chunk_f16(As, As + ASTAGE_B, acc, wm, wn, g, j);
    }
    __syncthreads();

    float* Cs = (float*)smc;
    #pragma unroll
    for (int mt = 0; mt < 4; mt++)
        #pragma unroll
        for (int nt = 0; nt < 4; nt++) {
            int r = wm * 64 + mt * 16 + g, cc = wn * 32 + nt * 8 + 2 * j;
            *(float2*)&Cs[r * CST + cc]       = make_float2(acc[mt][nt][0], acc[mt][nt][1]);
            *(float2*)&Cs[(r + 8) * CST + cc] = make_float2(acc[mt][nt][2], acc[mt][nt][3]);
        }
    __syncthreads();

    #pragma unroll 4
    for (int i = 0; i < 16; i++) {
        int idx = tid + i * 128;             // 128 rows x 16 float4
        int r = idx >> 4, c4 = idx & 15;
        float4 v = *(float4*)&Cs[r * CST + c4 * 4];
        float4 bv = *(const float4*)&bo[n0 + c4 * 4];
        v.x += bv.x; v.y += bv.y; v.z += bv.z; v.w += bv.w;
        *(float4*)&outp[(size_t)(m0 + r) * HH + n0 + c4 * 4] = v;
    }
}

// ---------------------------------------------------------------------------
// Flash attention fp16: 128-row CTA tile, 4 warps x 32 rows, no-max softmax,
// 64 MMAs/warp/tile (half of tf32). All operands fp16 k-permuted; P packed
// directly from S C-frags (cvt.rn.f16x2). smem 67.6KB -> 2 CTAs/SM.
// ---------------------------------------------------------------------------
#define QB 0
#define KB (128*RSTB)                      // 22528
#define VB (KB + 2*64*RSTB)                // 45056
#define ATTN_SMEM (VB + 2*64*RSTB)         // 67584

__global__ __launch_bounds__(128, 2) void attn_kernel()
{
    extern __shared__ char smc[];
    const int qt = gridDim.x - 1 - blockIdx.x;   // big CTAs first
    const int head = blockIdx.y, b = blockIdx.z;
    const int tid = threadIdx.x, wid = tid >> 5, lane = tid & 31;
    const int g = lane >> 2, j = lane & 3;
    const int r0 = wid * 32;
    const size_t base  = (size_t)(b * NHH + head) * SS * HDD;
    const size_t basev = (size_t)(b * NHH + head) * HDD * SS;
    const int q0 = qt * 128;
    const int rA = q0 + r0 + g, rB = rA + 8, rC = rA + 16, rD = rA + 24;

    const unsigned sbase = smem_u32(smc);

    // stage Q (pre-scaled, permuted fp16) + K/V tile 0
    #pragma unroll
    for (int i = 0; i < 8; i++) {
        int idx = tid + i * 128, r = idx >> 3, c8 = idx & 7;
        cp16(sbase + QB + r * RSTB + c8 * 16, &g_q[base + (size_t)(q0 + r) * HDD + c8 * 8]);
    }
    #pragma unroll
    for (int i = 0; i < 4; i++) {
        int idx = tid + i * 128, r = idx >> 3, c8 = idx & 7;
        cp16(sbase + KB + r * RSTB + c8 * 16, &g_k[base + (size_t)r * HDD + c8 * 8]);
        cp16(sbase + VB + r * RSTB + c8 * 16, &g_vt[basev + (size_t)r * SS + c8 * 8]);
    }
    CP_COMMIT();

    const int ntiles = 2 * qt + 2;
    float oa0[8] = {}, oa1[8] = {}, oa2[8] = {}, oa3[8] = {};
    float ob0[8] = {}, ob1[8] = {}, ob2[8] = {}, ob3[8] = {};
    float lA = 0.0f, lB = 0.0f, lC = 0.0f, lD = 0.0f;

    for (int kt = 0; kt < ntiles; kt++) {
        const int bf = kt & 1;
        CP_WAIT0();
        __syncthreads();                 // the only barrier in the loop

        if (kt + 1 < ntiles) {
            const int nb = bf ^ 1, k0n = (kt + 1) * 64;
            #pragma unroll
            for (int i = 0; i < 4; i++) {
                int idx = tid + i * 128, r = idx >> 3, c8 = idx & 7;
                cp16(sbase + KB + (nb * 64 + r) * RSTB + c8 * 16,
                     &g_k[base + (size_t)(k0n + r) * HDD + c8 * 8]);
                cp16(sbase + VB + (nb * 64 + r) * RSTB + c8 * 16,
                     &g_vt[basev + (size_t)r * SS + k0n + c8 * 8]);
            }
            CP_COMMIT();
        }
        const int k0 = kt * 64;
        if (k0 > q0 + r0 + 31) continue;         // warp fully masked

        const char* Qs = smc + QB;
        const char* Kb = smc + KB + bf * 64 * RSTB;
        const char* Vb = smc + VB + bf * 64 * RSTB;

        // S = Q K^T : 4 k-groups x 8 nt x 2 row-blocks = 64 MMAs
        float sa0[8] = {}, sa1[8] = {}, sa2[8] = {}, sa3[8] = {};
        float sb0[8] = {}, sb1[8] = {}, sb2[8] = {}, sb3[8] = {};
        #pragma unroll
        for (int kg = 0; kg < 4; kg++) {
            const int kb2 = (kg * 16 + 4 * j) * 2;
            uint2 qa = *(const uint2*)(Qs + (r0 + g)      * RSTB + kb2);
            uint2 qb = *(const uint2*)(Qs + (r0 + g + 8)  * RSTB + kb2);
            uint2 qc = *(const uint2*)(Qs + (r0 + g + 16) * RSTB + kb2);
            uint2 qd = *(const uint2*)(Qs + (r0 + g + 24) * RSTB + kb2);
            #pragma unroll
            for (int nt = 0; nt < 8; nt++) {
                uint2 kv = *(const uint2*)(Kb + (nt * 8 + g) * RSTB + kb2);
                mma_f16(sa0[nt], sa1[nt], sa2[nt], sa3[nt],
                        qa.x, qb.x, qa.y, qb.y, kv.x, kv.y);
                mma_f16(sb0[nt], sb1[nt], sb2[nt], sb3[nt],
                        qc.x, qd.x, qc.y, qd.y, kv.x, kv.y);
            }
        }

        // mask + no-max softmax (p = exp2(s), l accumulated per-thread)
        const bool dmA = (k0 + 63) > (q0 + r0);
        const bool dmB = (k0 + 63) > (q0 + r0 + 16);
        #pragma unroll
        for (int nt = 0; nt < 8; nt++) {
            int col = k0 + nt * 8 + 2 * j;
            if (dmA) {
                if (col     > rA) sa0[nt] = -1.0e30f;
                if (col + 1 > rA) sa1[nt] = -1.0e30f;
                if (col     > rB) sa2[nt] = -1.0e30f;
                if (col + 1 > rB) sa3[nt] = -1.0e30f;
            }
            if (dmB) {
                if (col     > rC) sb0[nt] = -1.0e30f;
                if (col + 1 > rC) sb1[nt] = -1.0e30f;
                if (col     > rD) sb2[nt] = -1.0e30f;
                if (col + 1 > rD) sb3[nt] = -1.0e30f;
            }
            float p0 = ex2(sa0[nt]), p1 = ex2(sa1[nt]);
            float p2 = ex2(sa2[nt]), p3 = ex2(sa3[nt]);
            float p4 = ex2(sb0[nt]), p5 = ex2(sb1[nt]);
            float p6 = ex2(sb2[nt]), p7 = ex2(sb3[nt]);
            lA += p0 + p1; lB += p2 + p3; lC += p4 + p5; lD += p6 + p7;
            sa0[nt] = p0; sa1[nt] = p1; sa2[nt] = p2; sa3[nt] = p3;
            sb0[nt] = p4; sb1[nt] = p5; sb2[nt] = p6; sb3[nt] = p7;
        }

        // O += P @ V : A-frags packed from S C-frags; 4 k-groups x 8 nt x 2
        #pragma unroll
        for (int t = 0; t < 4; t++) {
            unsigned a0 = pack_h2(sa0[2*t],     sa1[2*t]);
            unsigned a2 = pack_h2(sa0[2*t + 1], sa1[2*t + 1]);
            unsigned a1 = pack_h2(sa2[2*t],     sa3[2*t]);
            unsigned a3 = pack_h2(sa2[2*t + 1], sa3[2*t + 1]);
            unsigned c0 = pack_h2(sb0[2*t],     sb1[2*t]);
            unsigned c2 = pack_h2(sb0[2*t + 1], sb1[2*t + 1]);
            unsigned c1 = pack_h2(sb2[2*t],     sb3[2*t]);
            unsigned c3 = pack_h2(sb2[2*t + 1], sb3[2*t + 1]);
            const int kb2 = (t * 16 + 4 * j) * 2;
            #pragma unroll
            for (int nt = 0; nt < 8; nt++) {
                uint2 vv = *(const uint2*)(Vb + (nt * 8 + g) * RSTB + kb2);
                mma_f16(oa0[nt], oa1[nt], oa2[nt], oa3[nt],
                        a0, a1, a2, a3, vv.x, vv.y);
                mma_f16(ob0[nt], ob1[nt], ob2[nt], ob3[nt],
                        c0, c1, c2, c3, vv.x, vv.y);
            }
        }
    }

    // final l reduction (once)
    lA += __shfl_xor_sync(0xffffffffu, lA, 1);
    lA += __shfl_xor_sync(0xffffffffu, lA, 2);
    lB += __shfl_xor_sync(0xffffffffu, lB, 1);
    lB += __shfl_xor_sync(0xffffffffu, lB, 2);
    lC += __shfl_xor_sync(0xffffffffu, lC, 1);
    lC += __shfl_xor_sync(0xffffffffu, lC, 2);
    lD += __shfl_xor_sync(0xffffffffu, lD, 1);
    lD += __shfl_xor_sync(0xffffffffu, lD, 2);

    {
        float liA = 1.0f / lA, liB = 1.0f / lB, liC = 1.0f / lC, liD = 1.0f / lD;
        __half* ga = (__half*)g_attn;
        #pragma unroll
        for (int nt = 0; nt < 8; nt++) {
            int col = nt * 8 + 2 * j;
            int poff = (col & ~15) + KPOS(col & 15);   // adjacent pair positions
            *(unsigned*)(ga + base + (size_t)rA * HDD + poff) =
                pack_h2(oa0[nt] * liA, oa1[nt] * liA);
            *(unsigned*)(ga + base + (size_t)rB * HDD + poff) =
                pack_h2(oa2[nt] * liB, oa3[nt] * liB);
            *(unsigned*)(ga + base + (size_t)rC * HDD + poff) =
                pack_h2(ob0[nt] * liC, ob1[nt] * liC);
            *(unsigned*)(ga + base + (size_t)rD * HDD + poff) =
                pack_h2(ob2[nt] * liD, ob3[nt] * liD);
        }
    }
}

// ---------------------------------------------------------------------------
extern "C" void kernel_launch(void* const* d_in, const int* in_sizes, int n_in,
                              void* d_out, int out_size)
{
    const float* hs = (const float*)d_in[0];
    // d_in[1] = attention_mask (fixed causal) -- handled analytically
    const float* wq = (const float*)d_in[2];
    const float* bq = (const float*)d_in[3];
    const float* wk = (const float*)d_in[4];
    const float* bk = (const float*)d_in[5];
    const float* wv = (const float*)d_in[6];
    const float* bv = (const float*)d_in[7];
    const float* wo = (const float*)d_in[8];
    const float* bo = (const float*)d_in[9];
    float* out = (float*)d_out;

    prep_kernel<<<(MM * KK / 16) / 256, 256>>>(hs);
    pre_round_w<<<dim3(KK / 32, HH / 32, 4), dim3(32, 8)>>>(wq, wk, wv, wo);

    cudaFuncSetAttribute(qkv_mma,  cudaFuncAttributeMaxDynamicSharedMemorySize, GEMM_SMEM);
    cudaFuncSetAttribute(proj_mma, cudaFuncAttributeMaxDynamicSharedMemorySize, GEMM_SMEM);
    cudaFuncSetAttribute(attn_kernel, cudaFuncAttributeMaxDynamicSharedMemorySize, ATTN_SMEM);

    qkv_mma<<<dim3(NHH, 32, 3), 128, GEMM_SMEM>>>(bq, bk, bv);
    attn_kernel<<<dim3(SS / 128, NHH, BB), 128, ATTN_SMEM>>>();
    proj_mma<<<dim3(NHH, 32), 128, GEMM_SMEM>>>(bo, out);
}

// round 14
// speedup vs baseline: 1.5527x; 1.0215x over previous
#include <cuda_runtime.h>
#include <cuda_fp16.h>
#include <math.h>

// ---------------------------------------------------------------------------
// Problem constants
// ---------------------------------------------------------------------------
#define BB   2
#define SS   2048
#define HH   1024
#define NHH  16
#define HDD  64
#define MM   (BB*SS)      // 4096
#define KK   1024

// k-permutation within each 16-group: thread j's m16n8k16 fragment halves
// {2j,2j+1,2j+8,2j+9} become contiguous -> single LDS.64 per fragment.
#define KPOS(k) ((((k)&6)<<1) + ((((k)>>3)&1)<<1) + ((k)&1))

// Scratch (device globals) — fp16, k-permuted where contracted
__device__ __half g_q[BB*NHH*SS*HDD];     // [b,h,s,d] d-permuted, pre-scaled
__device__ __half g_k[BB*NHH*SS*HDD];     // [b,h,s,d] d-permuted
__device__ __half g_vt[BB*NHH*HDD*SS];    // [b,h,d,s] s-permuted
__device__ __half g_attn[BB*NHH*SS*HDD];  // [b,h,s,d] d-permuted
__device__ __half g_hs[MM*KK];            // [m][k]    k-permuted
__device__ __half g_wqt[HH*KK];           // [n][k]    k-permuted
__device__ __half g_wkt[HH*KK];
__device__ __half g_wvt[HH*KK];
__device__ __half g_wot[HH*KK];
__device__ float  g_cost[SS*32];
__device__ float  g_sint[SS*32];

// ---------------------------------------------------------------------------
// Helpers
// ---------------------------------------------------------------------------
__device__ __forceinline__ unsigned pack_h2(float lo, float hi) {
    unsigned r;
    asm("cvt.rn.f16x2.f32 %0, %1, %2;" : "=r"(r) : "f"(hi), "f"(lo));
    return r;
}
__device__ __forceinline__ unsigned ex2h2(unsigned x) {
    unsigned r;
    asm("ex2.approx.f16x2 %0, %1;" : "=r"(r) : "r"(x));
    return r;
}
__device__ __forceinline__ void mma_f16(float& c0, float& c1, float& c2, float& c3,
                                        unsigned a0, unsigned a1, unsigned a2, unsigned a3,
                                        unsigned b0, unsigned b1) {
    asm volatile(
        "mma.sync.aligned.m16n8k16.row.col.f32.f16.f16.f32 "
        "{%0,%1,%2,%3}, {%4,%5,%6,%7}, {%8,%9}, {%0,%1,%2,%3};"
        : "+f"(c0), "+f"(c1), "+f"(c2), "+f"(c3)
        : "r"(a0), "r"(a1), "r"(a2), "r"(a3), "r"(b0), "r"(b1));
}
__device__ __forceinline__ unsigned smem_u32(const void* p) {
    unsigned a;
    asm("{ .reg .u64 t; cvta.to.shared.u64 t, %1; cvt.u32.u64 %0, t; }"
        : "=r"(a) : "l"(p));
    return a;
}
__device__ __forceinline__ void cp16(unsigned s, const void* g) {
    asm volatile("cp.async.cg.shared.global [%0], [%1], 16;" :: "r"(s), "l"(g));
}
#define CP_COMMIT() asm volatile("cp.async.commit_group;" ::: "memory")
#define CP_WAIT0()  asm volatile("cp.async.wait_group 0;" ::: "memory")

// ---------------------------------------------------------------------------
// Prep: hidden fp32 -> fp16 k-permuted; RoPE table
// ---------------------------------------------------------------------------
__global__ void prep_kernel(const float* __restrict__ hs) {
    int i = blockIdx.x * blockDim.x + threadIdx.x;   // 0..262143
    const float4* src = (const float4*)(hs + (size_t)i * 16);
    float4 v0 = src[0], v1 = src[1], v2 = src[2], v3 = src[3];
    uint4 o0, o1;
    o0.x = pack_h2(v0.x, v0.y);   // pos 0,1   = k0,1
    o0.y = pack_h2(v2.x, v2.y);   // pos 2,3   = k8,9
    o0.z = pack_h2(v0.z, v0.w);   // pos 4,5   = k2,3
    o0.w = pack_h2(v2.z, v2.w);   // pos 6,7   = k10,11
    o1.x = pack_h2(v1.x, v1.y);   // pos 8,9   = k4,5
    o1.y = pack_h2(v3.x, v3.y);   // pos 10,11 = k12,13
    o1.z = pack_h2(v1.z, v1.w);   // pos 12,13 = k6,7
    o1.w = pack_h2(v3.z, v3.w);   // pos 14,15 = k14,15
    uint4* dst = (uint4*)(g_hs + (size_t)i * 16);
    dst[0] = o0; dst[1] = o1;

    if (i < SS * 32) {
        int s = i >> 5, j = i & 31;
        float inv = expf(-((float)(2 * j) / 64.0f) * 9.210340371976184f);
        float ang = (float)s * inv;
        float c, sn;
        sincosf(ang, &sn, &c);
        g_cost[i] = c;
        g_sint[i] = sn;
    }
}

// ---------------------------------------------------------------------------
// Transpose + fp16 + k-permute the 4 weight matrices: [k][n] -> [n][k]
// ---------------------------------------------------------------------------
__global__ void pre_round_w(const float* __restrict__ wq, const float* __restrict__ wk,
                            const float* __restrict__ wv, const float* __restrict__ wo) {
    __shared__ float t[32][33];
    const int z = blockIdx.z;
    const float* src = (z == 0) ? wq : (z == 1) ? wk : (z == 2) ? wv : wo;
    __half* dst = (z == 0) ? g_wqt : (z == 1) ? g_wkt : (z == 2) ? g_wvt : g_wot;
    const int k0 = blockIdx.x * 32, n0 = blockIdx.y * 32;
    #pragma unroll
    for (int i = 0; i < 4; i++) {
        int ky = threadIdx.y + i * 8;
        t[ky][threadIdx.x] = src[(size_t)(k0 + ky) * HH + n0 + threadIdx.x];
    }
    __syncthreads();
    int kx = threadIdx.x;
    int kp = k0 + (kx & ~15) + KPOS(kx & 15);
    #pragma unroll
    for (int i = 0; i < 4; i++) {
        int ny = threadIdx.y + i * 8;
        dst[(size_t)(n0 + ny) * KK + kp] = __float2half_rn(t[kx][ny]);
    }
}

// ---------------------------------------------------------------------------
// fp16 mma GEMM: 128x128 CTA tile (2 heads), k-chunk 64, 16 chunks,
// 128 threads, 4 warps x (64x64), 2-stage cp.async. 128 MMAs per wait.
// Row stride 88 halves (176B), conflict-free LDS.64. smem 90KB -> 2 CTAs/SM.
// ---------------------------------------------------------------------------
#define RSTB 176                          // row stride bytes (88 halves)
#define ASTAGE_B (128*RSTB)               // 22528
#define BSTAGE_B (128*RSTB)               // 22528
#define STAGE_B  (ASTAGE_B + BSTAGE_B)    // 45056
#define GEMM_SMEM (2 * STAGE_B)           // 90112
#define CST 132

__device__ __forceinline__ void gemm_chunk_f16(const char* As, const char* Bs,
                                               float acc[4][8][4],
                                               int wm, int wn, int g, int j) {
    #pragma unroll
    for (int kg = 0; kg < 4; kg++) {
        const int kb = (kg * 16 + 4 * j) * 2;
        uint2 a[4][2], bv[8];
        #pragma unroll
        for (int mt = 0; mt < 4; mt++) {
            int r = wm * 64 + mt * 16 + g;
            a[mt][0] = *(const uint2*)(As + r * RSTB + kb);
            a[mt][1] = *(const uint2*)(As + (r + 8) * RSTB + kb);
        }
        #pragma unroll
        for (int nt = 0; nt < 8; nt++) {
            int rr = wn * 64 + nt * 8 + g;
            bv[nt] = *(const uint2*)(Bs + rr * RSTB + kb);
        }
        #pragma unroll
        for (int mt = 0; mt < 4; mt++)
            #pragma unroll
            for (int nt = 0; nt < 8; nt++)
                mma_f16(acc[mt][nt][0], acc[mt][nt][1], acc[mt][nt][2], acc[mt][nt][3],
                        a[mt][0].x, a[mt][1].x, a[mt][0].y, a[mt][1].y,
                        bv[nt].x, bv[nt].y);
    }
}

// which: 0=q(rope,scaled) 1=k(rope) 2=v(transposed). n-tile = TWO heads.
__global__ __launch_bounds__(128) void qkv_mma(
    const float* __restrict__ bq, const float* __restrict__ bk, const float* __restrict__ bv)
{
    extern __shared__ char smc[];
    const int which = blockIdx.z;
    const __half* WT  = (which == 0) ? g_wqt : (which == 1) ? g_wkt : g_wvt;
    const float* bias = (which == 0) ? bq    : (which == 1) ? bk    : bv;

    const int head0 = blockIdx.x * 2;
    const int n0 = head0 * 64, m0 = blockIdx.y * 128;
    const int tid = threadIdx.x, wid = tid >> 5, lane = tid & 31;
    const int g = lane >> 2, j = lane & 3;
    const int wm = wid & 1, wn = wid >> 1;
    const unsigned sb = smem_u32(smc);

    auto stage = [&](int c) {
        const int k0 = c * 64;
        const unsigned bufb = sb + (c & 1) * STAGE_B;
        #pragma unroll
        for (int i = 0; i < 8; i++) {
            int idx = tid + i * 128, r = idx >> 3, c8 = idx & 7;
            cp16(bufb + r * RSTB + c8 * 16, &g_hs[(size_t)(m0 + r) * KK + k0 + c8 * 8]);
        }
        #pragma unroll
        for (int i = 0; i < 8; i++) {
            int idx = tid + i * 128, r = idx >> 3, c8 = idx & 7;
            cp16(bufb + ASTAGE_B + r * RSTB + c8 * 16,
                 &WT[(size_t)(n0 + r) * KK + k0 + c8 * 8]);
        }
        CP_COMMIT();
    };

    float acc[4][8][4] = {};
    stage(0);
    for (int c = 0; c < 16; c++) {
        CP_WAIT0();
        __syncthreads();
        if (c < 15) stage(c + 1);
        const char* As = smc + (c & 1) * STAGE_B;
        gemm_chunk_f16(As, As + ASTAGE_B, acc, wm, wn, g, j);
    }
    __syncthreads();

    float* Cs = (float*)smc;
    #pragma unroll
    for (int mt = 0; mt < 4; mt++)
        #pragma unroll
        for (int nt = 0; nt < 8; nt++) {
            int r = wm * 64 + mt * 16 + g, cc = wn * 64 + nt * 8 + 2 * j;
            *(float2*)&Cs[r * CST + cc]       = make_float2(acc[mt][nt][0], acc[mt][nt][1]);
            *(float2*)&Cs[(r + 8) * CST + cc] = make_float2(acc[mt][nt][2], acc[mt][nt][3]);
        }
    __syncthreads();

    const float QSCALE = 0.125f * 1.4426950408889634f;
    if (which != 2) {
        __half* out = (which == 0) ? g_q : g_k;
        const float scale = (which == 0) ? QSCALE : 1.0f;
        #pragma unroll 4
        for (int it = 0; it < 64; it++) {
            int p = it * 128 + tid;          // 128 rows x 64 pairs
            int r = p >> 6, hh = (p >> 5) & 1, jj = p & 31;
            int m = m0 + r, bb = m >> 11, s = m & 2047;
            int head = head0 + hh;
            float x1 = Cs[r * CST + hh * 64 + jj]      + bias[head * 64 + jj];
            float x2 = Cs[r * CST + hh * 64 + jj + 32] + bias[head * 64 + jj + 32];
            float cs = g_cost[s * 32 + jj], sn = g_sint[s * 32 + jj];
            __half* op = out + ((size_t)(bb * NHH + head) * SS + s) * HDD;
            int d1 = jj, d2 = jj + 32;
            op[(d1 & ~15) + KPOS(d1 & 15)] = __float2half_rn((x1 * cs - x2 * sn) * scale);
            op[(d2 & ~15) + KPOS(d2 & 15)] = __float2half_rn((x1 * sn + x2 * cs) * scale);
        }
    } else {
        #pragma unroll 4
        for (int it = 0; it < 128; it++) {
            int p = it * 128 + tid;          // 128 cols x 128 rows
            int r = p & 127, cc = p >> 7;
            int m = m0 + r, bb = m >> 11, s = m & 2047;
            int head = head0 + (cc >> 6), d = cc & 63;
            int spos = (s & ~15) + KPOS(s & 15);
            g_vt[((size_t)(bb * NHH + head) * HDD + d) * SS + spos] =
                __float2half_rn(Cs[r * CST + cc] + bias[head * 64 + d]);
        }
    }
}

__global__ __launch_bounds__(128) void proj_mma(
    const float* __restrict__ bo, float* __restrict__ outp)
{
    extern __shared__ char smc[];
    const int n0 = blockIdx.x * 128, m0 = blockIdx.y * 128;
    const int tid = threadIdx.x, wid = tid >> 5, lane = tid & 31;
    const int g = lane >> 2, j = lane & 3;
    const int wm = wid & 1, wn = wid >> 1;
    const unsigned sb = smem_u32(smc);

    auto stage = [&](int c) {
        const unsigned bufb = sb + (c & 1) * STAGE_B;
        #pragma unroll
        for (int i = 0; i < 8; i++) {
            int idx = tid + i * 128, r = idx >> 3, c8 = idx & 7;
            int m = m0 + r, bb = m >> 11, s = m & 2047;
            cp16(bufb + r * RSTB + c8 * 16,
                 &g_attn[((size_t)(bb * NHH + c) * SS + s) * HDD + c8 * 8]);
        }
        #pragma unroll
        for (int i = 0; i < 8; i++) {
            int idx = tid + i * 128, r = idx >> 3, c8 = idx & 7;
            cp16(bufb + ASTAGE_B + r * RSTB + c8 * 16,
                 &g_wot[(size_t)(n0 + r) * KK + c * 64 + c8 * 8]);
        }
        CP_COMMIT();
    };

    float acc[4][8][4] = {};
    stage(0);
    for (int c = 0; c < 16; c++) {
        CP_WAIT0();
        __syncthreads();
        if (c < 15) stage(c + 1);
        const char* As = smc + (c & 1) * STAGE_B;
        gemm_chunk_f16(As, As + ASTAGE_B, acc, wm, wn, g, j);
    }
    __syncthreads();

    float* Cs = (float*)smc;
    #pragma unroll
    for (int mt = 0; mt < 4; mt++)
        #pragma unroll
        for (int nt = 0; nt < 8; nt++) {
            int r = wm * 64 + mt * 16 + g, cc = wn * 64 + nt * 8 + 2 * j;
            *(float2*)&Cs[r * CST + cc]       = make_float2(acc[mt][nt][0], acc[mt][nt][1]);
            *(float2*)&Cs[(r + 8) * CST + cc] = make_float2(acc[mt][nt][2], acc[mt][nt][3]);
        }
    __syncthreads();

    #pragma unroll 4
    for (int i = 0; i < 32; i++) {
        int idx = tid + i * 128;             // 128 rows x 32 float4
        int r = idx >> 5, c4 = idx & 31;
        float4 v = *(float4*)&Cs[r * CST + c4 * 4];
        float4 bv = *(const float4*)&bo[n0 + c4 * 4];
        v.x += bv.x; v.y += bv.y; v.z += bv.z; v.w += bv.w;
        *(float4*)&outp[(size_t)(m0 + r) * HH + n0 + c4 * 4] = v;
    }
}

// ---------------------------------------------------------------------------
// Flash attention fp16: 128-row CTA tile, 4 warps x 32 rows, no-max softmax.
// l computed BY THE TENSOR CORE via a ones-column appended to V (nt=8).
// ex2.approx.f16x2 produces PV A-fragments directly. 2 CTAs/SM.
// ---------------------------------------------------------------------------
#define QB 0
#define KB (128*RSTB)                      // K: 2 x 64 rows
#define VB (KB + 128*RSTB)                 // V: 2 x 72 rows (64 data + ones/zeros)
#define VROWS 72
#define ATTN_SMEM (VB + 2*VROWS*RSTB)      // 70400 B

__global__ __launch_bounds__(128, 2) void attn_kernel()
{
    extern __shared__ char smc[];
    const int qt = gridDim.x - 1 - blockIdx.x;   // big CTAs first
    const int head = blockIdx.y, b = blockIdx.z;
    const int tid = threadIdx.x, wid = tid >> 5, lane = tid & 31;
    const int g = lane >> 2, j = lane & 3;
    const int r0 = wid * 32;
    const size_t base  = (size_t)(b * NHH + head) * SS * HDD;
    const size_t basev = (size_t)(b * NHH + head) * HDD * SS;
    const int q0 = qt * 128;
    const int rA = q0 + r0 + g, rB = rA + 8, rC = rA + 16, rD = rA + 24;

    const unsigned sbase = smem_u32(smc);

    // ones/zeros rows 64..71 of BOTH V buffers (row 64 = 1.0h, rest = 0)
    {
        unsigned* vrows = (unsigned*)(smc + VB);
        for (int idx = tid; idx < 2 * 8 * 44; idx += 128) {
            int buf = idx / (8 * 44);
            int rem = idx - buf * 8 * 44;
            int row = rem / 44, w = rem % 44;
            vrows[(buf * VROWS + 64 + row) * 44 + w] = (row == 0) ? 0x3C003C00u : 0u;
        }
    }

    // stage Q (pre-scaled, permuted fp16) + K/V tile 0
    #pragma unroll
    for (int i = 0; i < 8; i++) {
        int idx = tid + i * 128, r = idx >> 3, c8 = idx & 7;
        cp16(sbase + QB + r * RSTB + c8 * 16, &g_q[base + (size_t)(q0 + r) * HDD + c8 * 8]);
    }
    #pragma unroll
    for (int i = 0; i < 4; i++) {
        int idx = tid + i * 128, r = idx >> 3, c8 = idx & 7;
        cp16(sbase + KB + r * RSTB + c8 * 16, &g_k[base + (size_t)r * HDD + c8 * 8]);
        cp16(sbase + VB + r * RSTB + c8 * 16, &g_vt[basev + (size_t)r * SS + c8 * 8]);
    }
    CP_COMMIT();

    const int ntiles = 2 * qt + 2;
    float oa0[9] = {}, oa1[9] = {}, oa2[9] = {}, oa3[9] = {};
    float ob0[9] = {}, ob1[9] = {}, ob2[9] = {}, ob3[9] = {};

    for (int kt = 0; kt < ntiles; kt++) {
        const int bf = kt & 1;
        CP_WAIT0();
        __syncthreads();                 // the only barrier in the loop

        if (kt + 1 < ntiles) {
            const int nb = bf ^ 1, k0n = (kt + 1) * 64;
            #pragma unroll
            for (int i = 0; i < 4; i++) {
                int idx = tid + i * 128, r = idx >> 3, c8 = idx & 7;
                cp16(sbase + KB + (nb * 64 + r) * RSTB + c8 * 16,
                     &g_k[base + (size_t)(k0n + r) * HDD + c8 * 8]);
                cp16(sbase + VB + (nb * VROWS + r) * RSTB + c8 * 16,
                     &g_vt[basev + (size_t)r * SS + k0n + c8 * 8]);
            }
            CP_COMMIT();
        }
        const int k0 = kt * 64;
        if (k0 > q0 + r0 + 31) continue;         // warp fully masked

        const char* Qs = smc + QB;
        const char* Kb = smc + KB + bf * 64 * RSTB;
        const char* Vb = smc + VB + bf * VROWS * RSTB;

        // S = Q K^T
        float sa0[8] = {}, sa1[8] = {}, sa2[8] = {}, sa3[8] = {};
        float sb0[8] = {}, sb1[8] = {}, sb2[8] = {}, sb3[8] = {};
        #pragma unroll
        for (int kg = 0; kg < 4; kg++) {
            const int kb2 = (kg * 16 + 4 * j) * 2;
            uint2 qa = *(const uint2*)(Qs + (r0 + g)      * RSTB + kb2);
            uint2 qb = *(const uint2*)(Qs + (r0 + g + 8)  * RSTB + kb2);
            uint2 qc = *(const uint2*)(Qs + (r0 + g + 16) * RSTB + kb2);
            uint2 qd = *(const uint2*)(Qs + (r0 + g + 24) * RSTB + kb2);
            #pragma unroll
            for (int nt = 0; nt < 8; nt++) {
                uint2 kv = *(const uint2*)(Kb + (nt * 8 + g) * RSTB + kb2);
                mma_f16(sa0[nt], sa1[nt], sa2[nt], sa3[nt],
                        qa.x, qb.x, qa.y, qb.y, kv.x, kv.y);
                mma_f16(sb0[nt], sb1[nt], sb2[nt], sb3[nt],
                        qc.x, qd.x, qc.y, qd.y, kv.x, kv.y);
            }
        }

        // mask + p = exp2(s) in fp16x2 -> directly the PV A-fragments
        const bool dmA = (k0 + 63) > (q0 + r0);
        const bool dmB = (k0 + 63) > (q0 + r0 + 16);
        unsigned ua01[8], ua23[8], ub01[8], ub23[8];
        #pragma unroll
        for (int nt = 0; nt < 8; nt++) {
            int col = k0 + nt * 8 + 2 * j;
            if (dmA) {
                if (col     > rA) sa0[nt] = -1.0e30f;
                if (col + 1 > rA) sa1[nt] = -1.0e30f;
                if (col     > rB) sa2[nt] = -1.0e30f;
                if (col + 1 > rB) sa3[nt] = -1.0e30f;
            }
            if (dmB) {
                if (col     > rC) sb0[nt] = -1.0e30f;
                if (col + 1 > rC) sb1[nt] = -1.0e30f;
                if (col     > rD) sb2[nt] = -1.0e30f;
                if (col + 1 > rD) sb3[nt] = -1.0e30f;
            }
            ua01[nt] = ex2h2(pack_h2(sa0[nt], sa1[nt]));
            ua23[nt] = ex2h2(pack_h2(sa2[nt], sa3[nt]));
            ub01[nt] = ex2h2(pack_h2(sb0[nt], sb1[nt]));
            ub23[nt] = ex2h2(pack_h2(sb2[nt], sb3[nt]));
        }

        // O += P @ V  (nt=8 is the ones-column: accumulates l in fp32)
        #pragma unroll
        for (int t = 0; t < 4; t++) {
            const int kb2 = (t * 16 + 4 * j) * 2;
            unsigned a0 = ua01[2*t], a2 = ua01[2*t + 1];
            unsigned a1 = ua23[2*t], a3 = ua23[2*t + 1];
            unsigned c0 = ub01[2*t], c2 = ub01[2*t + 1];
            unsigned c1 = ub23[2*t], c3 = ub23[2*t + 1];
            #pragma unroll
            for (int nt = 0; nt < 9; nt++) {
                uint2 vv = *(const uint2*)(Vb + (nt * 8 + g) * RSTB + kb2);
                mma_f16(oa0[nt], oa1[nt], oa2[nt], oa3[nt],
                        a0, a1, a2, a3, vv.x, vv.y);
                mma_f16(ob0[nt], ob1[nt], ob2[nt], ob3[nt],
                        c0, c1, c2, c3, vv.x, vv.y);
            }
        }
    }

    // l lives in column 64 (nt=8, j=0 lanes): broadcast within each quad
    {
        const unsigned src = lane & ~3u;
        float lA = __shfl_sync(0xffffffffu, oa0[8], src);
        float lB = __shfl_sync(0xffffffffu, oa2[8], src);
        float lC = __shfl_sync(0xffffffffu, ob0[8], src);
        float lD = __shfl_sync(0xffffffffu, ob2[8], src);
        float liA = 1.0f / lA, liB = 1.0f / lB, liC = 1.0f / lC, liD = 1.0f / lD;
        __half* ga = (__half*)g_attn;
        #pragma unroll
        for (int nt = 0; nt < 8; nt++) {
            int col = nt * 8 + 2 * j;
            int poff = (col & ~15) + KPOS(col & 15);   // adjacent pair positions
            *(unsigned*)(ga + base + (size_t)rA * HDD + poff) =
                pack_h2(oa0[nt] * liA, oa1[nt] * liA);
            *(unsigned*)(ga + base + (size_t)rB * HDD + poff) =
                pack_h2(oa2[nt] * liB, oa3[nt] * liB);
            *(unsigned*)(ga + base + (size_t)rC * HDD + poff) =
                pack_h2(ob0[nt] * liC, ob1[nt] * liC);
            *(unsigned*)(ga + base + (size_t)rD * HDD + poff) =
                pack_h2(ob2[nt] * liD, ob3[nt] * liD);
        }
    }
}

// ---------------------------------------------------------------------------
extern "C" void kernel_launch(void* const* d_in, const int* in_sizes, int n_in,
                              void* d_out, int out_size)
{
    const float* hs = (const float*)d_in[0];
    // d_in[1] = attention_mask (fixed causal) -- handled analytically
    const float* wq = (const float*)d_in[2];
    const float* bq = (const float*)d_in[3];
    const float* wk = (const float*)d_in[4];
    const float* bk = (const float*)d_in[5];
    const float* wv = (const float*)d_in[6];
    const float* bv = (const float*)d_in[7];
    const float* wo = (const float*)d_in[8];
    const float* bo = (const float*)d_in[9];
    float* out = (float*)d_out;

    prep_kernel<<<(MM * KK / 16) / 256, 256>>>(hs);
    pre_round_w<<<dim3(KK / 32, HH / 32, 4), dim3(32, 8)>>>(wq, wk, wv, wo);

    cudaFuncSetAttribute(qkv_mma,  cudaFuncAttributeMaxDynamicSharedMemorySize, GEMM_SMEM);
    cudaFuncSetAttribute(proj_mma, cudaFuncAttributeMaxDynamicSharedMemorySize, GEMM_SMEM);
    cudaFuncSetAttribute(attn_kernel, cudaFuncAttributeMaxDynamicSharedMemorySize, ATTN_SMEM);

    qkv_mma<<<dim3(NHH / 2, 32, 3), 128, GEMM_SMEM>>>(bq, bk, bv);
    attn_kernel<<<dim3(SS / 128, NHH, BB), 128, ATTN_SMEM>>>();
    proj_mma<<<dim3(NHH / 2, 32), 128, GEMM_SMEM>>>(bo, out);
}

// round 15
// speedup vs baseline: 1.5708x; 1.0117x over previous
#include <cuda_runtime.h>
#include <cuda_fp16.h>
#include <math.h>

// ---------------------------------------------------------------------------
// Problem constants
// ---------------------------------------------------------------------------
#define BB   2
#define SS   2048
#define HH   1024
#define NHH  16
#define HDD  64
#define MM   (BB*SS)      // 4096
#define KK   1024

// k-permutation within each 16-group: thread j's m16n8k16 fragment halves
// {2j,2j+1,2j+8,2j+9} become contiguous -> single LDS.64 per fragment.
#define KPOS(k) ((((k)&6)<<1) + ((((k)>>3)&1)<<1) + ((k)&1))

// Scratch (device globals) — fp16, k-permuted where contracted
__device__ __half g_q[BB*NHH*SS*HDD];     // [b,h,s,d] d-permuted, pre-scaled
__device__ __half g_k[BB*NHH*SS*HDD];     // [b,h,s,d] d-permuted
__device__ __half g_vt[BB*NHH*HDD*SS];    // [b,h,d,s] s-permuted
__device__ __half g_attn[BB*NHH*SS*HDD];  // [b,h,s,d] d-permuted
__device__ __half g_hs[MM*KK];            // [m][k]    k-permuted
__device__ __half g_wqt[HH*KK];           // [n][k]    k-permuted
__device__ __half g_wkt[HH*KK];
__device__ __half g_wvt[HH*KK];
__device__ __half g_wot[HH*KK];
__device__ float  g_cost[SS*32];
__device__ float  g_sint[SS*32];

// ---------------------------------------------------------------------------
// Helpers
// ---------------------------------------------------------------------------
__device__ __forceinline__ unsigned pack_h2(float lo, float hi) {
    unsigned r;
    asm("cvt.rn.f16x2.f32 %0, %1, %2;" : "=r"(r) : "f"(hi), "f"(lo));
    return r;
}
__device__ __forceinline__ unsigned ex2h2(unsigned x) {
    unsigned r;
    asm("ex2.approx.f16x2 %0, %1;" : "=r"(r) : "r"(x));
    return r;
}
__device__ __forceinline__ void mma_f16(float& c0, float& c1, float& c2, float& c3,
                                        unsigned a0, unsigned a1, unsigned a2, unsigned a3,
                                        unsigned b0, unsigned b1) {
    asm volatile(
        "mma.sync.aligned.m16n8k16.row.col.f32.f16.f16.f32 "
        "{%0,%1,%2,%3}, {%4,%5,%6,%7}, {%8,%9}, {%0,%1,%2,%3};"
        : "+f"(c0), "+f"(c1), "+f"(c2), "+f"(c3)
        : "r"(a0), "r"(a1), "r"(a2), "r"(a3), "r"(b0), "r"(b1));
}
__device__ __forceinline__ unsigned smem_u32(const void* p) {
    unsigned a;
    asm("{ .reg .u64 t; cvta.to.shared.u64 t, %1; cvt.u32.u64 %0, t; }"
        : "=r"(a) : "l"(p));
    return a;
}
__device__ __forceinline__ void cp16(unsigned s, const void* g) {
    asm volatile("cp.async.cg.shared.global [%0], [%1], 16;" :: "r"(s), "l"(g));
}
#define CP_COMMIT() asm volatile("cp.async.commit_group;" ::: "memory")
#define CP_WAIT0()  asm volatile("cp.async.wait_group 0;" ::: "memory")

// ---------------------------------------------------------------------------
// Prep: hidden fp32 -> fp16 k-permuted; RoPE table
// ---------------------------------------------------------------------------
__global__ void prep_kernel(const float* __restrict__ hs) {
    int i = blockIdx.x * blockDim.x + threadIdx.x;   // 0..262143
    const float4* src = (const float4*)(hs + (size_t)i * 16);
    float4 v0 = src[0], v1 = src[1], v2 = src[2], v3 = src[3];
    uint4 o0, o1;
    o0.x = pack_h2(v0.x, v0.y);   // pos 0,1   = k0,1
    o0.y = pack_h2(v2.x, v2.y);   // pos 2,3   = k8,9
    o0.z = pack_h2(v0.z, v0.w);   // pos 4,5   = k2,3
    o0.w = pack_h2(v2.z, v2.w);   // pos 6,7   = k10,11
    o1.x = pack_h2(v1.x, v1.y);   // pos 8,9   = k4,5
    o1.y = pack_h2(v3.x, v3.y);   // pos 10,11 = k12,13
    o1.z = pack_h2(v1.z, v1.w);   // pos 12,13 = k6,7
    o1.w = pack_h2(v3.z, v3.w);   // pos 14,15 = k14,15
    uint4* dst = (uint4*)(g_hs + (size_t)i * 16);
    dst[0] = o0; dst[1] = o1;

    if (i < SS * 32) {
        int s = i >> 5, j = i & 31;
        float inv = expf(-((float)(2 * j) / 64.0f) * 9.210340371976184f);
        float ang = (float)s * inv;
        float c, sn;
        sincosf(ang, &sn, &c);
        g_cost[i] = c;
        g_sint[i] = sn;
    }
}

// ---------------------------------------------------------------------------
// Transpose + fp16 + k-permute the 4 weight matrices: [k][n] -> [n][k]
// ---------------------------------------------------------------------------
__global__ void pre_round_w(const float* __restrict__ wq, const float* __restrict__ wk,
                            const float* __restrict__ wv, const float* __restrict__ wo) {
    __shared__ float t[32][33];
    const int z = blockIdx.z;
    const float* src = (z == 0) ? wq : (z == 1) ? wk : (z == 2) ? wv : wo;
    __half* dst = (z == 0) ? g_wqt : (z == 1) ? g_wkt : (z == 2) ? g_wvt : g_wot;
    const int k0 = blockIdx.x * 32, n0 = blockIdx.y * 32;
    #pragma unroll
    for (int i = 0; i < 4; i++) {
        int ky = threadIdx.y + i * 8;
        t[ky][threadIdx.x] = src[(size_t)(k0 + ky) * HH + n0 + threadIdx.x];
    }
    __syncthreads();
    int kx = threadIdx.x;
    int kp = k0 + (kx & ~15) + KPOS(kx & 15);
    #pragma unroll
    for (int i = 0; i < 4; i++) {
        int ny = threadIdx.y + i * 8;
        dst[(size_t)(n0 + ny) * KK + kp] = __float2half_rn(t[kx][ny]);
    }
}

// ---------------------------------------------------------------------------
// fp16 mma GEMM (unchanged from R14): 128x128 CTA tile (2 heads), k-chunk 64,
// 128 threads, 4 warps x (64x64), 2-stage cp.async, 128 MMAs per wait.
// ---------------------------------------------------------------------------
#define RSTB 176                          // row stride bytes (88 halves)
#define ASTAGE_B (128*RSTB)               // 22528
#define BSTAGE_B (128*RSTB)               // 22528
#define STAGE_B  (ASTAGE_B + BSTAGE_B)    // 45056
#define GEMM_SMEM (2 * STAGE_B)           // 90112
#define CST 132

__device__ __forceinline__ void gemm_chunk_f16(const char* As, const char* Bs,
                                               float acc[4][8][4],
                                               int wm, int wn, int g, int j) {
    #pragma unroll
    for (int kg = 0; kg < 4; kg++) {
        const int kb = (kg * 16 + 4 * j) * 2;
        uint2 a[4][2], bv[8];
        #pragma unroll
        for (int mt = 0; mt < 4; mt++) {
            int r = wm * 64 + mt * 16 + g;
            a[mt][0] = *(const uint2*)(As + r * RSTB + kb);
            a[mt][1] = *(const uint2*)(As + (r + 8) * RSTB + kb);
        }
        #pragma unroll
        for (int nt = 0; nt < 8; nt++) {
            int rr = wn * 64 + nt * 8 + g;
            bv[nt] = *(const uint2*)(Bs + rr * RSTB + kb);
        }
        #pragma unroll
        for (int mt = 0; mt < 4; mt++)
            #pragma unroll
            for (int nt = 0; nt < 8; nt++)
                mma_f16(acc[mt][nt][0], acc[mt][nt][1], acc[mt][nt][2], acc[mt][nt][3],
                        a[mt][0].x, a[mt][1].x, a[mt][0].y, a[mt][1].y,
                        bv[nt].x, bv[nt].y);
    }
}

// which: 0=q(rope,scaled) 1=k(rope) 2=v(transposed). n-tile = TWO heads.
__global__ __launch_bounds__(128) void qkv_mma(
    const float* __restrict__ bq, const float* __restrict__ bk, const float* __restrict__ bv)
{
    extern __shared__ char smc[];
    const int which = blockIdx.z;
    const __half* WT  = (which == 0) ? g_wqt : (which == 1) ? g_wkt : g_wvt;
    const float* bias = (which == 0) ? bq    : (which == 1) ? bk    : bv;

    const int head0 = blockIdx.x * 2;
    const int n0 = head0 * 64, m0 = blockIdx.y * 128;
    const int tid = threadIdx.x, wid = tid >> 5, lane = tid & 31;
    const int g = lane >> 2, j = lane & 3;
    const int wm = wid & 1, wn = wid >> 1;
    const unsigned sb = smem_u32(smc);

    auto stage = [&](int c) {
        const int k0 = c * 64;
        const unsigned bufb = sb + (c & 1) * STAGE_B;
        #pragma unroll
        for (int i = 0; i < 8; i++) {
            int idx = tid + i * 128, r = idx >> 3, c8 = idx & 7;
            cp16(bufb + r * RSTB + c8 * 16, &g_hs[(size_t)(m0 + r) * KK + k0 + c8 * 8]);
        }
        #pragma unroll
        for (int i = 0; i < 8; i++) {
            int idx = tid + i * 128, r = idx >> 3, c8 = idx & 7;
            cp16(bufb + ASTAGE_B + r * RSTB + c8 * 16,
                 &WT[(size_t)(n0 + r) * KK + k0 + c8 * 8]);
        }
        CP_COMMIT();
    };

    float acc[4][8][4] = {};
    stage(0);
    for (int c = 0; c < 16; c++) {
        CP_WAIT0();
        __syncthreads();
        if (c < 15) stage(c + 1);
        const char* As = smc + (c & 1) * STAGE_B;
        gemm_chunk_f16(As, As + ASTAGE_B, acc, wm, wn, g, j);
    }
    __syncthreads();

    float* Cs = (float*)smc;
    #pragma unroll
    for (int mt = 0; mt < 4; mt++)
        #pragma unroll
        for (int nt = 0; nt < 8; nt++) {
            int r = wm * 64 + mt * 16 + g, cc = wn * 64 + nt * 8 + 2 * j;
            *(float2*)&Cs[r * CST + cc]       = make_float2(acc[mt][nt][0], acc[mt][nt][1]);
            *(float2*)&Cs[(r + 8) * CST + cc] = make_float2(acc[mt][nt][2], acc[mt][nt][3]);
        }
    __syncthreads();

    const float QSCALE = 0.125f * 1.4426950408889634f;
    if (which != 2) {
        __half* out = (which == 0) ? g_q : g_k;
        const float scale = (which == 0) ? QSCALE : 1.0f;
        #pragma unroll 4
        for (int it = 0; it < 64; it++) {
            int p = it * 128 + tid;          // 128 rows x 64 pairs
            int r = p >> 6, hh = (p >> 5) & 1, jj = p & 31;
            int m = m0 + r, bb = m >> 11, s = m & 2047;
            int head = head0 + hh;
            float x1 = Cs[r * CST + hh * 64 + jj]      + bias[head * 64 + jj];
            float x2 = Cs[r * CST + hh * 64 + jj + 32] + bias[head * 64 + jj + 32];
            float cs = g_cost[s * 32 + jj], sn = g_sint[s * 32 + jj];
            __half* op = out + ((size_t)(bb * NHH + head) * SS + s) * HDD;
            int d1 = jj, d2 = jj + 32;
            op[(d1 & ~15) + KPOS(d1 & 15)] = __float2half_rn((x1 * cs - x2 * sn) * scale);
            op[(d2 & ~15) + KPOS(d2 & 15)] = __float2half_rn((x1 * sn + x2 * cs) * scale);
        }
    } else {
        #pragma unroll 4
        for (int it = 0; it < 128; it++) {
            int p = it * 128 + tid;          // 128 cols x 128 rows
            int r = p & 127, cc = p >> 7;
            int m = m0 + r, bb = m >> 11, s = m & 2047;
            int head = head0 + (cc >> 6), d = cc & 63;
            int spos = (s & ~15) + KPOS(s & 15);
            g_vt[((size_t)(bb * NHH + head) * HDD + d) * SS + spos] =
                __float2half_rn(Cs[r * CST + cc] + bias[head * 64 + d]);
        }
    }
}

__global__ __launch_bounds__(128) void proj_mma(
    const float* __restrict__ bo, float* __restrict__ outp)
{
    extern __shared__ char smc[];
    const int n0 = blockIdx.x * 128, m0 = blockIdx.y * 128;
    const int tid = threadIdx.x, wid = tid >> 5, lane = tid & 31;
    const int g = lane >> 2, j = lane & 3;
    const int wm = wid & 1, wn = wid >> 1;
    const unsigned sb = smem_u32(smc);

    auto stage = [&](int c) {
        const unsigned bufb = sb + (c & 1) * STAGE_B;
        #pragma unroll
        for (int i = 0; i < 8; i++) {
            int idx = tid + i * 128, r = idx >> 3, c8 = idx & 7;
            int m = m0 + r, bb = m >> 11, s = m & 2047;
            cp16(bufb + r * RSTB + c8 * 16,
                 &g_attn[((size_t)(bb * NHH + c) * SS + s) * HDD + c8 * 8]);
        }
        #pragma unroll
        for (int i = 0; i < 8; i++) {
            int idx = tid + i * 128, r = idx >> 3, c8 = idx & 7;
            cp16(bufb + ASTAGE_B + r * RSTB + c8 * 16,
                 &g_wot[(size_t)(n0 + r) * KK + c * 64 + c8 * 8]);
        }
        CP_COMMIT();
    };

    float acc[4][8][4] = {};
    stage(0);
    for (int c = 0; c < 16; c++) {
        CP_WAIT0();
        __syncthreads();
        if (c < 15) stage(c + 1);
        const char* As = smc + (c & 1) * STAGE_B;
        gemm_chunk_f16(As, As + ASTAGE_B, acc, wm, wn, g, j);
    }
    __syncthreads();

    float* Cs = (float*)smc;
    #pragma unroll
    for (int mt = 0; mt < 4; mt++)
        #pragma unroll
        for (int nt = 0; nt < 8; nt++) {
            int r = wm * 64 + mt * 16 + g, cc = wn * 64 + nt * 8 + 2 * j;
            *(float2*)&Cs[r * CST + cc]       = make_float2(acc[mt][nt][0], acc[mt][nt][1]);
            *(float2*)&Cs[(r + 8) * CST + cc] = make_float2(acc[mt][nt][2], acc[mt][nt][3]);
        }
    __syncthreads();

    #pragma unroll 4
    for (int i = 0; i < 32; i++) {
        int idx = tid + i * 128;             // 128 rows x 32 float4
        int r = idx >> 5, c4 = idx & 31;
        float4 v = *(float4*)&Cs[r * CST + c4 * 4];
        float4 bv = *(const float4*)&bo[n0 + c4 * 4];
        v.x += bv.x; v.y += bv.y; v.z += bv.z; v.w += bv.w;
        *(float4*)&outp[(size_t)(m0 + r) * HH + n0 + c4 * 4] = v;
    }
}

// ---------------------------------------------------------------------------
// Flash attention fp16 v2: Q fragments hoisted out of the KV loop (Q is
// tile-invariant), S->exp->PV fused per nt-pair to shrink live registers,
// tensor-core l (ones-column), f16x2 exp. __launch_bounds__(128,3):
// 3 CTAs/SM (smem 3x70.4KB = 211KB, regs capped at 170).
// ---------------------------------------------------------------------------
#define QB 0
#define KB (128*RSTB)                      // K: 2 x 64 rows
#define VB (KB + 128*RSTB)                 // V: 2 x 72 rows (64 data + ones/zeros)
#define VROWS 72
#define ATTN_SMEM (VB + 2*VROWS*RSTB)      // 70400 B

__global__ __launch_bounds__(128, 3) void attn_kernel()
{
    extern __shared__ char smc[];
    const int qt = gridDim.x - 1 - blockIdx.x;   // big CTAs first
    const int head = blockIdx.y, b = blockIdx.z;
    const int tid = threadIdx.x, wid = tid >> 5, lane = tid & 31;
    const int g = lane >> 2, j = lane & 3;
    const int r0 = wid * 32;
    const size_t base  = (size_t)(b * NHH + head) * SS * HDD;
    const size_t basev = (size_t)(b * NHH + head) * HDD * SS;
    const int q0 = qt * 128;
    const int rA = q0 + r0 + g, rB = rA + 8, rC = rA + 16, rD = rA + 24;

    const unsigned sbase = smem_u32(smc);

    // ones/zeros rows 64..71 of BOTH V buffers (row 64 = 1.0h, rest = 0)
    {
        unsigned* vrows = (unsigned*)(smc + VB);
        for (int idx = tid; idx < 2 * 8 * 44; idx += 128) {
            int buf = idx / (8 * 44);
            int rem = idx - buf * 8 * 44;
            int row = rem / 44, w = rem % 44;
            vrows[(buf * VROWS + 64 + row) * 44 + w] = (row == 0) ? 0x3C003C00u : 0u;
        }
    }

    // stage Q (pre-scaled, permuted fp16) + K/V tile 0
    #pragma unroll
    for (int i = 0; i < 8; i++) {
        int idx = tid + i * 128, r = idx >> 3, c8 = idx & 7;
        cp16(sbase + QB + r * RSTB + c8 * 16, &g_q[base + (size_t)(q0 + r) * HDD + c8 * 8]);
    }
    #pragma unroll
    for (int i = 0; i < 4; i++) {
        int idx = tid + i * 128, r = idx >> 3, c8 = idx & 7;
        cp16(sbase + KB + r * RSTB + c8 * 16, &g_k[base + (size_t)r * HDD + c8 * 8]);
        cp16(sbase + VB + r * RSTB + c8 * 16, &g_vt[basev + (size_t)r * SS + c8 * 8]);
    }
    CP_COMMIT();

    const int ntiles = 2 * qt + 2;
    float oa0[9] = {}, oa1[9] = {}, oa2[9] = {}, oa3[9] = {};
    float ob0[9] = {}, ob1[9] = {}, ob2[9] = {}, ob3[9] = {};
    uint2 qf[4][4];   // [row-group a,b,c,d][kg] — loaded once at kt==0

    for (int kt = 0; kt < ntiles; kt++) {
        const int bf = kt & 1;
        CP_WAIT0();
        __syncthreads();                 // the only barrier in the loop

        if (kt == 0) {
            const char* Qs = smc + QB;
            #pragma unroll
            for (int kg = 0; kg < 4; kg++) {
                const int kb2 = (kg * 16 + 4 * j) * 2;
                qf[0][kg] = *(const uint2*)(Qs + (r0 + g)      * RSTB + kb2);
                qf[1][kg] = *(const uint2*)(Qs + (r0 + g + 8)  * RSTB + kb2);
                qf[2][kg] = *(const uint2*)(Qs + (r0 + g + 16) * RSTB + kb2);
                qf[3][kg] = *(const uint2*)(Qs + (r0 + g + 24) * RSTB + kb2);
            }
        }

        if (kt + 1 < ntiles) {
            const int nb = bf ^ 1, k0n = (kt + 1) * 64;
            #pragma unroll
            for (int i = 0; i < 4; i++) {
                int idx = tid + i * 128, r = idx >> 3, c8 = idx & 7;
                cp16(sbase + KB + (nb * 64 + r) * RSTB + c8 * 16,
                     &g_k[base + (size_t)(k0n + r) * HDD + c8 * 8]);
                cp16(sbase + VB + (nb * VROWS + r) * RSTB + c8 * 16,
                     &g_vt[basev + (size_t)r * SS + k0n + c8 * 8]);
            }
            CP_COMMIT();
        }
        const int k0 = kt * 64;
        if (k0 > q0 + r0 + 31) continue;         // warp fully masked

        const char* Kb = smc + KB + bf * 64 * RSTB;
        const char* Vb = smc + VB + bf * VROWS * RSTB;
        const bool dmA = (k0 + 63) > (q0 + r0);
        const bool dmB = (k0 + 63) > (q0 + r0 + 16);

        // fused per nt-pair: S -> mask+exp -> PV (k-group p)
        #pragma unroll
        for (int p = 0; p < 4; p++) {
            float sa0[2] = {}, sa1[2] = {}, sa2[2] = {}, sa3[2] = {};
            float sb0[2] = {}, sb1[2] = {}, sb2[2] = {}, sb3[2] = {};
            #pragma unroll
            for (int kg = 0; kg < 4; kg++) {
                const int kb2 = (kg * 16 + 4 * j) * 2;
                #pragma unroll
                for (int u = 0; u < 2; u++) {
                    uint2 kv = *(const uint2*)(Kb + ((2 * p + u) * 8 + g) * RSTB + kb2);
                    mma_f16(sa0[u], sa1[u], sa2[u], sa3[u],
                            qf[0][kg].x, qf[1][kg].x, qf[0][kg].y, qf[1][kg].y,
                            kv.x, kv.y);
                    mma_f16(sb0[u], sb1[u], sb2[u], sb3[u],
                            qf[2][kg].x, qf[3][kg].x, qf[2][kg].y, qf[3][kg].y,
                            kv.x, kv.y);
                }
            }
            #pragma unroll
            for (int u = 0; u < 2; u++) {
                int col = k0 + (2 * p + u) * 8 + 2 * j;
                if (dmA) {
                    if (col     > rA) sa0[u] = -1.0e30f;
                    if (col + 1 > rA) sa1[u] = -1.0e30f;
                    if (col     > rB) sa2[u] = -1.0e30f;
                    if (col + 1 > rB) sa3[u] = -1.0e30f;
                }
                if (dmB) {
                    if (col     > rC) sb0[u] = -1.0e30f;
                    if (col + 1 > rC) sb1[u] = -1.0e30f;
                    if (col     > rD) sb2[u] = -1.0e30f;
                    if (col + 1 > rD) sb3[u] = -1.0e30f;
                }
            }
            unsigned a0 = ex2h2(pack_h2(sa0[0], sa1[0]));
            unsigned a2 = ex2h2(pack_h2(sa0[1], sa1[1]));
            unsigned a1 = ex2h2(pack_h2(sa2[0], sa3[0]));
            unsigned a3 = ex2h2(pack_h2(sa2[1], sa3[1]));
            unsigned c0 = ex2h2(pack_h2(sb0[0], sb1[0]));
            unsigned c2 = ex2h2(pack_h2(sb0[1], sb1[1]));
            unsigned c1 = ex2h2(pack_h2(sb2[0], sb3[0]));
            unsigned c3 = ex2h2(pack_h2(sb2[1], sb3[1]));

            const int kb2 = (p * 16 + 4 * j) * 2;
            #pragma unroll
            for (int nt = 0; nt < 9; nt++) {
                uint2 vv = *(const uint2*)(Vb + (nt * 8 + g) * RSTB + kb2);
                mma_f16(oa0[nt], oa1[nt], oa2[nt], oa3[nt],
                        a0, a1, a2, a3, vv.x, vv.y);
                mma_f16(ob0[nt], ob1[nt], ob2[nt], ob3[nt],
                        c0, c1, c2, c3, vv.x, vv.y);
            }
        }
    }

    // l lives in column 64 (nt=8, j=0 lanes): broadcast within each quad
    {
        const unsigned src = lane & ~3u;
        float lA = __shfl_sync(0xffffffffu, oa0[8], src);
        float lB = __shfl_sync(0xffffffffu, oa2[8], src);
        float lC = __shfl_sync(0xffffffffu, ob0[8], src);
        float lD = __shfl_sync(0xffffffffu, ob2[8], src);
        float liA = 1.0f / lA, liB = 1.0f / lB, liC = 1.0f / lC, liD = 1.0f / lD;
        __half* ga = (__half*)g_attn;
        #pragma unroll
        for (int nt = 0; nt < 8; nt++) {
            int col = nt * 8 + 2 * j;
            int poff = (col & ~15) + KPOS(col & 15);   // adjacent pair positions
            *(unsigned*)(ga + base + (size_t)rA * HDD + poff) =
                pack_h2(oa0[nt] * liA, oa1[nt] * liA);
            *(unsigned*)(ga + base + (size_t)rB * HDD + poff) =
                pack_h2(oa2[nt] * liB, oa3[nt] * liB);
            *(unsigned*)(ga + base + (size_t)rC * HDD + poff) =
                pack_h2(ob0[nt] * liC, ob1[nt] * liC);
            *(unsigned*)(ga + base + (size_t)rD * HDD + poff) =
                pack_h2(ob2[nt] * liD, ob3[nt] * liD);
        }
    }
}

// ---------------------------------------------------------------------------
extern "C" void kernel_launch(void* const* d_in, const int* in_sizes, int n_in,
                              void* d_out, int out_size)
{
    const float* hs = (const float*)d_in[0];
    // d_in[1] = attention_mask (fixed causal) -- handled analytically
    const float* wq = (const float*)d_in[2];
    const float* bq = (const float*)d_in[3];
    const float* wk = (const float*)d_in[4];
    const float* bk = (const float*)d_in[5];
    const float* wv = (const float*)d_in[6];
    const float* bv = (const float*)d_in[7];
    const float* wo = (const float*)d_in[8];
    const float* bo = (const float*)d_in[9];
    float* out = (float*)d_out;

    prep_kernel<<<(MM * KK / 16) / 256, 256>>>(hs);
    pre_round_w<<<dim3(KK / 32, HH / 32, 4), dim3(32, 8)>>>(wq, wk, wv, wo);

    cudaFuncSetAttribute(qkv_mma,  cudaFuncAttributeMaxDynamicSharedMemorySize, GEMM_SMEM);
    cudaFuncSetAttribute(proj_mma, cudaFuncAttributeMaxDynamicSharedMemorySize, GEMM_SMEM);
    cudaFuncSetAttribute(attn_kernel, cudaFuncAttributeMaxDynamicSharedMemorySize, ATTN_SMEM);

    qkv_mma<<<dim3(NHH / 2, 32, 3), 128, GEMM_SMEM>>>(bq, bk, bv);
    attn_kernel<<<dim3(SS / 128, NHH, BB), 128, ATTN_SMEM>>>();
    proj_mma<<<dim3(NHH / 2, 32), 128, GEMM_SMEM>>>(bo, out);
}